// round 11
// baseline (speedup 1.0000x reference)
#include <cuda_runtime.h>
#include <cuda_bf16.h>
#include <math.h>
#include <stdint.h>

#define N_NODES 10000
#define E_EDGES 160000
#define C_IN    256
#define C_MID   512

// ---------------- scratch (static __device__ allocations only) ----------------
// Invariants across calls (zero at module load, restored every call):
//   d_cnt == 0   (re-zeroed by k_fill after its readers ran)
//   d_sum == 0   (reset by k_bnfinal after consumption)
__device__ float d_agx[(size_t)N_NODES * C_IN];    // Â x           (256-wide)
__device__ float d_h1 [(size_t)N_NODES * C_MID];   // (Âx) W1^T     (pre-BN)
__device__ float d_xl2[(size_t)N_NODES * C_IN];    // h1n W2^T
__device__ float d_h2 [(size_t)N_NODES * C_IN];    // Â xl2         (pre-BN)
__device__ int   d_cnt[N_NODES];
__device__ int   d_off[N_NODES + 1];
__device__ int   d_cur[N_NODES];
__device__ float d_dis[N_NODES];                   // deg^-0.5 (incl self loop)
__device__ int   d_esrc[E_EDGES];                  // CSR-by-dst source rows
__device__ float d_sum[2 * C_MID];                 // BN sums: [0..F)=sum, [F..2F)=sumsq
__device__ float d_ab [2 * C_MID];                 // BN affine: [0..F)=a, [F..2F)=b

// ---------------- helpers ----------------
__device__ __forceinline__ uint32_t s2u(const void* p) {
    return (uint32_t)__cvta_generic_to_shared(p);
}
__device__ __forceinline__ void bfsplit(float x, __nv_bfloat16& h, __nv_bfloat16& l) {
    h = __float2bfloat16(x);
    l = __float2bfloat16(x - __bfloat162float(h));
}
__device__ __forceinline__ uint32_t pkbf(__nv_bfloat16 a, __nv_bfloat16 b) {
    __nv_bfloat162 v; v.x = a; v.y = b;
    return *(uint32_t*)&v;
}
__device__ __forceinline__ void ldm_x4(uint32_t& r0, uint32_t& r1, uint32_t& r2,
                                       uint32_t& r3, uint32_t addr) {
    asm volatile("ldmatrix.sync.aligned.m8n8.x4.shared.b16 {%0,%1,%2,%3}, [%4];"
                 : "=r"(r0), "=r"(r1), "=r"(r2), "=r"(r3) : "r"(addr));
}
__device__ __forceinline__ void mma_bf16(float* d, const uint32_t* a,
                                         uint32_t b0, uint32_t b1) {
    asm volatile(
        "mma.sync.aligned.m16n8k16.row.col.f32.bf16.bf16.f32 "
        "{%0,%1,%2,%3}, {%4,%5,%6,%7}, {%8,%9}, {%0,%1,%2,%3};"
        : "+f"(d[0]), "+f"(d[1]), "+f"(d[2]), "+f"(d[3])
        : "r"(a[0]), "r"(a[1]), "r"(a[2]), "r"(a[3]), "r"(b0), "r"(b1));
}

// ---------------- degree count (in-degree over col); d_cnt==0 on entry -------
// 2 edges per thread, vectorized int2 read of the col half.
__global__ void k_count(const int* __restrict__ es) {
    int t = blockIdx.x * blockDim.x + threadIdx.x;
    if (t < E_EDGES / 2) {
        const int2 c2 = *(const int2*)&es[E_EDGES + t * 2];
        unsigned c0 = (unsigned)c2.x, c1 = (unsigned)c2.y;
        if (c0 < N_NODES) atomicAdd(&d_cnt[c0], 1);
        if (c1 < N_NODES) atomicAdd(&d_cnt[c1], 1);
    }
}

// ---------------- exclusive scan (single block) + dis ----------------
__global__ void k_scan() {
    __shared__ int sh[1024];
    int t = threadIdx.x;
    const int CH = (N_NODES + 1023) / 1024;  // 10
    int base = t * CH;
    int loc = 0;
    for (int i = 0; i < CH; i++) {
        int idx = base + i;
        if (idx < N_NODES) loc += d_cnt[idx];
    }
    sh[t] = loc;
    __syncthreads();
    for (int s = 1; s < 1024; s <<= 1) {
        int v = (t >= s) ? sh[t - s] : 0;
        __syncthreads();
        sh[t] += v;
        __syncthreads();
    }
    int run = (t == 0) ? 0 : sh[t - 1];
    for (int i = 0; i < CH; i++) {
        int idx = base + i;
        if (idx < N_NODES) {
            d_off[idx] = run;
            d_cur[idx] = run;
            int c = d_cnt[idx];
            d_dis[idx] = rsqrtf((float)(c + 1));   // +1 self loop; always > 0
            run += c;
        }
    }
    if (t == 1023) d_off[N_NODES] = sh[1023];
}

// ---------------- CSR fill (2 edges/thread) + restore d_cnt==0 ---------------
__global__ void k_fill(const int* __restrict__ es) {
    int t = blockIdx.x * blockDim.x + threadIdx.x;
    if (t * 2 < N_NODES) {                  // readers (count/scan) already ran
        d_cnt[t * 2] = 0;
        if (t * 2 + 1 < N_NODES) d_cnt[t * 2 + 1] = 0;
    }
    if (t < E_EDGES / 2) {
        const int2 r2 = *(const int2*)&es[t * 2];
        const int2 c2 = *(const int2*)&es[E_EDGES + t * 2];
        unsigned r0 = (unsigned)r2.x, c0 = (unsigned)c2.x;
        unsigned r1 = (unsigned)r2.y, c1 = (unsigned)c2.y;
        if (r0 < N_NODES && c0 < N_NODES) {
            int p = atomicAdd(&d_cur[c0], 1);
            d_esrc[p] = (int)r0;
        }
        if (r1 < N_NODES && c1 < N_NODES) {
            int p = atomicAdd(&d_cur[c1], 1);
            d_esrc[p] = (int)r1;
        }
    }
}

// ---------------- CSR gather (wide grid: 2 nodes/block, 8x edge unroll) ------
// MODE 1: in = x (param), out = d_agx.
// MODE 2: in = d_xl2, out = d_h2, fused BN stats (block-reduced atomics).
template <int MODE>
__global__ __launch_bounds__(128) void k_agg(const float* __restrict__ xin) {
    const float* __restrict__ in = (MODE == 1) ? xin : d_xl2;
    float* __restrict__ out = (MODE == 1) ? d_agx : d_h2;

    const int v = blockIdx.x * 2 + (threadIdx.x >> 6);   // 64 threads per node
    const int off = (threadIdx.x & 63) * 4;              // always valid: N even

    float a0 = 0.f, a1 = 0.f, a2 = 0.f, a3 = 0.f;
    const int beg = d_off[v], end = d_off[v + 1];
    const float dv = d_dis[v];

    int e = beg;
    for (; e + 7 < end; e += 8) {
        int   s[8]; float w[8]; float4 q[8];
#pragma unroll
        for (int i = 0; i < 8; i++) s[i] = d_esrc[e + i];
#pragma unroll
        for (int i = 0; i < 8; i++) w[i] = d_dis[s[i]];
#pragma unroll
        for (int i = 0; i < 8; i++)
            q[i] = *(const float4*)&in[(size_t)s[i] * C_IN + off];
#pragma unroll
        for (int i = 0; i < 8; i++) {
            a0 = fmaf(w[i], q[i].x, a0); a1 = fmaf(w[i], q[i].y, a1);
            a2 = fmaf(w[i], q[i].z, a2); a3 = fmaf(w[i], q[i].w, a3);
        }
    }
    for (; e < end; e++) {
        const int s = d_esrc[e];
        const float w = d_dis[s];
        const float4 q = *(const float4*)&in[(size_t)s * C_IN + off];
        a0 = fmaf(w, q.x, a0); a1 = fmaf(w, q.y, a1);
        a2 = fmaf(w, q.z, a2); a3 = fmaf(w, q.w, a3);
    }
    {   // self loop
        const float4 q = *(const float4*)&in[(size_t)v * C_IN + off];
        a0 = fmaf(dv, q.x, a0); a1 = fmaf(dv, q.y, a1);
        a2 = fmaf(dv, q.z, a2); a3 = fmaf(dv, q.w, a3);
    }
    const float h0 = dv * a0, h1 = dv * a1, h2 = dv * a2, h3 = dv * a3;
    *(float4*)&out[(size_t)v * C_IN + off] = make_float4(h0, h1, h2, h3);

    if (MODE == 2) {
        // block reduction across the two node-halves, then atomics
        __shared__ float red[64][8];
        const int fl = threadIdx.x & 63;
        if (threadIdx.x >= 64) {
            red[fl][0] = h0; red[fl][1] = h1; red[fl][2] = h2; red[fl][3] = h3;
            red[fl][4] = h0 * h0; red[fl][5] = h1 * h1;
            red[fl][6] = h2 * h2; red[fl][7] = h3 * h3;
        }
        __syncthreads();
        if (threadIdx.x < 64) {
            atomicAdd(&d_sum[off + 0], h0 + red[fl][0]);
            atomicAdd(&d_sum[off + 1], h1 + red[fl][1]);
            atomicAdd(&d_sum[off + 2], h2 + red[fl][2]);
            atomicAdd(&d_sum[off + 3], h3 + red[fl][3]);
            atomicAdd(&d_sum[C_IN + off + 0], fmaf(h0, h0, red[fl][4]));
            atomicAdd(&d_sum[C_IN + off + 1], fmaf(h1, h1, red[fl][5]));
            atomicAdd(&d_sum[C_IN + off + 2], fmaf(h2, h2, red[fl][6]));
            atomicAdd(&d_sum[C_IN + off + 3], fmaf(h3, h3, red[fl][7]));
        }
    }
}

// ---------------- Tensor-core NT GEMM (bf16-split, fp32-quality) -------------
// C[M,N] = A[M,K] * B[N,K]^T.  Block 128x128, BK=32, 8 warps (2x4), warp 64x32.
// D += Ah*Bh + Ah*Bl + Al*Bh.
// LAYER 1: A = d_agx, C = d_h1, fused BN-stats atomics into d_sum.
// LAYER 2: A = d_h1 (+fused relu(a*v+b) on load), C = d_xl2.
template <int K, int LAYER>
__global__ __launch_bounds__(256) void k_gemm(const float* __restrict__ B,
                                              int M, int Ncols)
{
    const float* __restrict__ A = (LAYER == 1) ? d_agx : d_h1;
    float* __restrict__ Cm = (LAYER == 1) ? d_h1 : d_xl2;

    constexpr int BK  = 32;
    constexpr int LDS = 40;                    // halves per smem row (80B stride)
    __shared__ __nv_bfloat16 sAh[128 * LDS];
    __shared__ __nv_bfloat16 sAl[128 * LDS];
    __shared__ __nv_bfloat16 sBh[128 * LDS];
    __shared__ __nv_bfloat16 sBl[128 * LDS];

    const int bm = blockIdx.y * 128, bn = blockIdx.x * 128;
    const int tid = threadIdx.x;
    const int lane = tid & 31, wid = tid >> 5;
    const int mw = wid >> 2, nw = wid & 3;     // warp grid 2(m) x 4(n)

    float acc[4][4][4];
#pragma unroll
    for (int i = 0; i < 4; i++)
#pragma unroll
        for (int j = 0; j < 4; j++)
#pragma unroll
            for (int q = 0; q < 4; q++) acc[i][j][q] = 0.f;

    const int grow = tid >> 1;                 // 0..127
    const int gk   = (tid & 1) * 16;           // 0 or 16

    float4 ra[4], rb[4];
    auto gload = [&](int k0) {
        const int arow = bm + grow;
        if (arow < M) {
#pragma unroll
            for (int i = 0; i < 4; i++)
                ra[i] = *(const float4*)&A[(size_t)arow * K + k0 + gk + i * 4];
        } else {
#pragma unroll
            for (int i = 0; i < 4; i++) ra[i] = make_float4(0.f, 0.f, 0.f, 0.f);
        }
        if (LAYER == 2) {
#pragma unroll
            for (int i = 0; i < 4; i++) {
                const int kb = k0 + gk + i * 4;
                const float4 s4 = *(const float4*)&d_ab[kb];
                const float4 t4 = *(const float4*)&d_ab[C_MID + kb];
                ra[i].x = fmaxf(fmaf(ra[i].x, s4.x, t4.x), 0.f);
                ra[i].y = fmaxf(fmaf(ra[i].y, s4.y, t4.y), 0.f);
                ra[i].z = fmaxf(fmaf(ra[i].z, s4.z, t4.z), 0.f);
                ra[i].w = fmaxf(fmaf(ra[i].w, s4.w, t4.w), 0.f);
            }
        }
        const int brow = bn + grow;
#pragma unroll
        for (int i = 0; i < 4; i++)
            rb[i] = *(const float4*)&B[(size_t)brow * K + k0 + gk + i * 4];
    };

    auto sstore = [&]() {
        const int base = grow * LDS + gk;
#pragma unroll
        for (int i = 0; i < 4; i++) {
            __nv_bfloat16 h0, l0, h1, l1, h2, l2, h3, l3;
            bfsplit(ra[i].x, h0, l0); bfsplit(ra[i].y, h1, l1);
            bfsplit(ra[i].z, h2, l2); bfsplit(ra[i].w, h3, l3);
            *(uint2*)&sAh[base + i * 4] = make_uint2(pkbf(h0, h1), pkbf(h2, h3));
            *(uint2*)&sAl[base + i * 4] = make_uint2(pkbf(l0, l1), pkbf(l2, l3));
            bfsplit(rb[i].x, h0, l0); bfsplit(rb[i].y, h1, l1);
            bfsplit(rb[i].z, h2, l2); bfsplit(rb[i].w, h3, l3);
            *(uint2*)&sBh[base + i * 4] = make_uint2(pkbf(h0, h1), pkbf(h2, h3));
            *(uint2*)&sBl[base + i * 4] = make_uint2(pkbf(l0, l1), pkbf(l2, l3));
        }
    };

    const uint32_t uAh = s2u(sAh), uAl = s2u(sAl);
    const uint32_t uBh = s2u(sBh), uBl = s2u(sBl);

    gload(0);
    constexpr int NT = K / BK;
#pragma unroll 1
    for (int kt = 0; kt < NT; kt++) {
        __syncthreads();
        sstore();
        __syncthreads();
        if (kt + 1 < NT) gload((kt + 1) * BK);

#pragma unroll
        for (int ks = 0; ks < 2; ks++) {
            const int koff = ks * 16 + ((lane & 16) ? 8 : 0);
            uint32_t Bh0[8], Bl0[8];
#pragma unroll
            for (int nf2 = 0; nf2 < 2; nf2++) {
                const int row = nw * 32 + nf2 * 16 + (lane & 15);
                const uint32_t ad = (uint32_t)(row * LDS + koff) * 2;
                ldm_x4(Bh0[nf2*4+0], Bh0[nf2*4+1], Bh0[nf2*4+2], Bh0[nf2*4+3], uBh + ad);
                ldm_x4(Bl0[nf2*4+0], Bl0[nf2*4+1], Bl0[nf2*4+2], Bl0[nf2*4+3], uBl + ad);
            }
#pragma unroll
            for (int mf = 0; mf < 4; mf++) {
                const int arow = mw * 64 + mf * 16 + (lane & 15);
                const uint32_t ad = (uint32_t)(arow * LDS + koff) * 2;
                uint32_t Ah[4], Al[4];
                ldm_x4(Ah[0], Ah[1], Ah[2], Ah[3], uAh + ad);
                ldm_x4(Al[0], Al[1], Al[2], Al[3], uAl + ad);
#pragma unroll
                for (int nf = 0; nf < 4; nf++) {
                    const int b = (nf >> 1) * 4 + (nf & 1);
                    const uint32_t bh0 = Bh0[b], bh1 = Bh0[b + 2];
                    const uint32_t bl0 = Bl0[b], bl1 = Bl0[b + 2];
                    mma_bf16(acc[mf][nf], Ah, bh0, bh1);
                    mma_bf16(acc[mf][nf], Ah, bl0, bl1);
                    mma_bf16(acc[mf][nf], Al, bh0, bh1);
                }
            }
        }
    }

    // epilogue: store C (+ fused BN stats for LAYER 1)
#pragma unroll
    for (int mf = 0; mf < 4; mf++) {
        const int r0 = bm + mw * 64 + mf * 16 + (lane >> 2);
        const int r1 = r0 + 8;
#pragma unroll
        for (int nf = 0; nf < 4; nf++) {
            const int col = bn + nw * 32 + nf * 8 + (lane & 3) * 2;
            if (r0 < M)
                *(float2*)&Cm[(size_t)r0 * Ncols + col] =
                    make_float2(acc[mf][nf][0], acc[mf][nf][1]);
            if (r1 < M)
                *(float2*)&Cm[(size_t)r1 * Ncols + col] =
                    make_float2(acc[mf][nf][2], acc[mf][nf][3]);
        }
    }
    if (LAYER == 1) {
        // per-thread partial sums over its 8 columns (rows >= M contribute 0)
        float s[8], q[8];
#pragma unroll
        for (int c = 0; c < 8; c++) { s[c] = 0.f; q[c] = 0.f; }
#pragma unroll
        for (int mf = 0; mf < 4; mf++)
#pragma unroll
            for (int nf = 0; nf < 4; nf++)
#pragma unroll
                for (int pair = 0; pair < 2; pair++) {
                    const int c = nf * 2 + pair;
                    const float v0 = acc[mf][nf][pair];       // row r0
                    const float v1 = acc[mf][nf][2 + pair];   // row r1
                    s[c] += v0 + v1;
                    q[c] = fmaf(v0, v0, q[c]);
                    q[c] = fmaf(v1, v1, q[c]);
                }
        // reduce across the 8 row-lane groups (lane>>2)
#pragma unroll
        for (int off = 4; off < 32; off <<= 1)
#pragma unroll
            for (int c = 0; c < 8; c++) {
                s[c] += __shfl_xor_sync(0xffffffffu, s[c], off);
                q[c] += __shfl_xor_sync(0xffffffffu, q[c], off);
            }
        if (lane < 4) {
#pragma unroll
            for (int c = 0; c < 8; c++) {
                const int col = bn + nw * 32 + (c >> 1) * 8 + lane * 2 + (c & 1);
                atomicAdd(&d_sum[col], s[c]);
                atomicAdd(&d_sum[C_MID + col], q[c]);
            }
        }
    }
}

// ---------------- BN finalize (also restores d_sum==0 invariant) -------------
__global__ void k_bnfinal(const float* __restrict__ g, const float* __restrict__ be, int F) {
    const int f = threadIdx.x + blockIdx.x * blockDim.x;
    if (f >= F) return;
    const float invN = 1.f / (float)N_NODES;
    const float s = d_sum[f], q = d_sum[F + f];
    const float m = s * invN;
    const float var = q * invN - m * m;
    const float a = g[f] * rsqrtf(var + 1e-5f);
    d_ab[f] = a;
    d_ab[F + f] = be[f] - m * a;
    d_sum[f] = 0.f;
    d_sum[F + f] = 0.f;
}

// ---------------- final: out = relu(a2*h2 + b2 + x) ----------------
__global__ __launch_bounds__(256) void k_final(const float* __restrict__ x,
                                               float* __restrict__ out) {
    const int idx = blockIdx.x * 256 + threadIdx.x;
    const int f = threadIdx.x;
    const float v = fmaf(d_ab[f], d_h2[idx], d_ab[C_IN + f]) + x[idx];
    out[idx] = fmaxf(v, 0.f);
}

// ---------------- launcher (kernel launches ONLY — graph-capture safe) --------
extern "C" void kernel_launch(void* const* d_in, const int* in_sizes, int n_in,
                              void* d_out, int out_size) {
    (void)in_sizes; (void)n_in; (void)out_size;
    const float* x  = (const float*)d_in[0];
    const int*   es = (const int*)d_in[1];      // int32 edge list [2, E]
    const float* W1 = (const float*)d_in[2];
    const float* g1 = (const float*)d_in[3];
    const float* b1 = (const float*)d_in[4];
    const float* W2 = (const float*)d_in[5];
    const float* g2 = (const float*)d_in[6];
    const float* b2 = (const float*)d_in[7];
    float* out = (float*)d_out;

    // graph structure (d_cnt==0 invariant on entry)
    k_count<<<(E_EDGES / 2 + 255) / 256, 256>>>(es);
    k_scan<<<1, 1024>>>();
    k_fill<<<(E_EDGES / 2 + 255) / 256, 256>>>(es);

    // layer 1: aggregate x -> TC GEMM (+BN stats fused) -> BN finalize
    k_agg<1><<<(N_NODES + 1) / 2, 128>>>(x);
    {
        dim3 grid(C_MID / 128, (N_NODES + 127) / 128);   // (4, 79)
        k_gemm<C_IN, 1><<<grid, 256>>>(W1, N_NODES, C_MID);
    }
    k_bnfinal<<<1, C_MID>>>(g1, b1, C_MID);

    // layer 2: (BN+ReLU fused) TC GEMM -> aggregate (+BN stats fused) -> BN -> out
    {
        dim3 grid(C_IN / 128, (N_NODES + 127) / 128);    // (2, 79)
        k_gemm<C_MID, 2><<<grid, 256>>>(W2, N_NODES, C_IN);
    }
    k_agg<2><<<(N_NODES + 1) / 2, 128>>>(nullptr);
    k_bnfinal<<<1, C_IN>>>(g2, b2, C_IN);
    k_final<<<N_NODES, 256>>>(x, out);
}

// round 12
// speedup vs baseline: 1.8784x; 1.8784x over previous
#include <cuda_runtime.h>
#include <cuda_bf16.h>
#include <math.h>
#include <stdint.h>

#define N_NODES 10000
#define E_EDGES 160000
#define C_IN    256
#define C_MID   512

// ---------------- scratch (static __device__ allocations only) ----------------
// Invariants across calls (zero at module load, restored every call):
//   d_cnt == 0   (re-zeroed by k_fill after its readers ran)
//   d_sum == 0   (reset by k_bnfinal after consumption)
__device__ float d_agx[(size_t)N_NODES * C_IN];    // Â x           (256-wide)
__device__ float d_h1 [(size_t)N_NODES * C_MID];   // (Âx) W1^T     (pre-BN)
__device__ float d_xl2[(size_t)N_NODES * C_IN];    // h1n W2^T
__device__ float d_h2 [(size_t)N_NODES * C_IN];    // Â xl2         (pre-BN)
__device__ int   d_cnt[N_NODES];
__device__ int   d_off[N_NODES + 1];
__device__ int   d_cur[N_NODES];
__device__ float d_dis[N_NODES];                   // deg^-0.5 (incl self loop)
__device__ int2  d_epk[E_EDGES];                   // packed {src, bits(dis[src])}
__device__ float d_sum[2 * C_MID];                 // BN sums: [0..F)=sum, [F..2F)=sumsq
__device__ float d_ab [2 * C_MID];                 // BN affine: [0..F)=a, [F..2F)=b

// ---------------- helpers ----------------
__device__ __forceinline__ uint32_t s2u(const void* p) {
    return (uint32_t)__cvta_generic_to_shared(p);
}
__device__ __forceinline__ void bfsplit(float x, __nv_bfloat16& h, __nv_bfloat16& l) {
    h = __float2bfloat16(x);
    l = __float2bfloat16(x - __bfloat162float(h));
}
__device__ __forceinline__ uint32_t pkbf(__nv_bfloat16 a, __nv_bfloat16 b) {
    __nv_bfloat162 v; v.x = a; v.y = b;
    return *(uint32_t*)&v;
}
__device__ __forceinline__ void ldm_x4(uint32_t& r0, uint32_t& r1, uint32_t& r2,
                                       uint32_t& r3, uint32_t addr) {
    asm volatile("ldmatrix.sync.aligned.m8n8.x4.shared.b16 {%0,%1,%2,%3}, [%4];"
                 : "=r"(r0), "=r"(r1), "=r"(r2), "=r"(r3) : "r"(addr));
}
__device__ __forceinline__ void mma_bf16(float* d, const uint32_t* a,
                                         uint32_t b0, uint32_t b1) {
    asm volatile(
        "mma.sync.aligned.m16n8k16.row.col.f32.bf16.bf16.f32 "
        "{%0,%1,%2,%3}, {%4,%5,%6,%7}, {%8,%9}, {%0,%1,%2,%3};"
        : "+f"(d[0]), "+f"(d[1]), "+f"(d[2]), "+f"(d[3])
        : "r"(a[0]), "r"(a[1]), "r"(a[2]), "r"(a[3]), "r"(b0), "r"(b1));
}

// ---------------- degree count (in-degree over col); d_cnt==0 on entry -------
__global__ void k_count(const int* __restrict__ es) {
    int e = blockIdx.x * blockDim.x + threadIdx.x;
    if (e < E_EDGES) {
        unsigned c = (unsigned)es[E_EDGES + e];
        if (c < N_NODES) atomicAdd(&d_cnt[c], 1);
    }
}

// ---------------- exclusive scan (single block) + dis ----------------
__global__ void k_scan() {
    __shared__ int sh[1024];
    int t = threadIdx.x;
    const int CH = (N_NODES + 1023) / 1024;  // 10
    int base = t * CH;
    int loc = 0;
    for (int i = 0; i < CH; i++) {
        int idx = base + i;
        if (idx < N_NODES) loc += d_cnt[idx];
    }
    sh[t] = loc;
    __syncthreads();
    for (int s = 1; s < 1024; s <<= 1) {
        int v = (t >= s) ? sh[t - s] : 0;
        __syncthreads();
        sh[t] += v;
        __syncthreads();
    }
    int run = (t == 0) ? 0 : sh[t - 1];
    for (int i = 0; i < CH; i++) {
        int idx = base + i;
        if (idx < N_NODES) {
            d_off[idx] = run;
            d_cur[idx] = run;
            int c = d_cnt[idx];
            d_dis[idx] = rsqrtf((float)(c + 1));   // +1 self loop; always > 0
            run += c;
        }
    }
    if (t == 1023) d_off[N_NODES] = sh[1023];
}

// ---------------- CSR fill (packed src+weight) + restore d_cnt==0 ------------
// d_dis is ready (k_scan ran), so fold the source weight into the edge record.
__global__ void k_fill(const int* __restrict__ es) {
    int e = blockIdx.x * blockDim.x + threadIdx.x;
    if (e < N_NODES) d_cnt[e] = 0;     // readers (count/scan) already ran
    if (e < E_EDGES) {
        unsigned r = (unsigned)es[e];
        unsigned c = (unsigned)es[E_EDGES + e];
        if (r < N_NODES && c < N_NODES) {
            int p = atomicAdd(&d_cur[c], 1);
            d_epk[p] = make_int2((int)r, __float_as_int(d_dis[r]));
        }
    }
}

// ---------------- CSR gather (wide grid: 2 nodes/block, 4x edge unroll) ------
// One 8B packed load per edge (src + weight) — no dependent dis[] gather.
// MODE 1: in = x (param), out = d_agx.   MODE 2: in = d_xl2, out = d_h2.
template <int MODE>
__global__ __launch_bounds__(128) void k_agg(const float* __restrict__ xin) {
    const float* __restrict__ in = (MODE == 1) ? xin : d_xl2;
    float* __restrict__ out = (MODE == 1) ? d_agx : d_h2;

    const int v = blockIdx.x * 2 + (threadIdx.x >> 6);   // 64 threads per node
    const int off = (threadIdx.x & 63) * 4;
    if (v >= N_NODES) return;

    float a0 = 0.f, a1 = 0.f, a2 = 0.f, a3 = 0.f;
    const int beg = d_off[v], end = d_off[v + 1];
    const float dv = d_dis[v];

    int e = beg;
    for (; e + 3 < end; e += 4) {
        const int2 p0 = d_epk[e + 0], p1 = d_epk[e + 1];
        const int2 p2 = d_epk[e + 2], p3 = d_epk[e + 3];
        const float w0 = __int_as_float(p0.y), w1 = __int_as_float(p1.y);
        const float w2 = __int_as_float(p2.y), w3 = __int_as_float(p3.y);
        const float4 q0 = *(const float4*)&in[(size_t)p0.x * C_IN + off];
        const float4 q1 = *(const float4*)&in[(size_t)p1.x * C_IN + off];
        const float4 q2 = *(const float4*)&in[(size_t)p2.x * C_IN + off];
        const float4 q3 = *(const float4*)&in[(size_t)p3.x * C_IN + off];
        a0 = fmaf(w0, q0.x, a0); a1 = fmaf(w0, q0.y, a1);
        a2 = fmaf(w0, q0.z, a2); a3 = fmaf(w0, q0.w, a3);
        a0 = fmaf(w1, q1.x, a0); a1 = fmaf(w1, q1.y, a1);
        a2 = fmaf(w1, q1.z, a2); a3 = fmaf(w1, q1.w, a3);
        a0 = fmaf(w2, q2.x, a0); a1 = fmaf(w2, q2.y, a1);
        a2 = fmaf(w2, q2.z, a2); a3 = fmaf(w2, q2.w, a3);
        a0 = fmaf(w3, q3.x, a0); a1 = fmaf(w3, q3.y, a1);
        a2 = fmaf(w3, q3.z, a2); a3 = fmaf(w3, q3.w, a3);
    }
    for (; e < end; e++) {
        const int2 p = d_epk[e];
        const float w = __int_as_float(p.y);
        const float4 q = *(const float4*)&in[(size_t)p.x * C_IN + off];
        a0 = fmaf(w, q.x, a0); a1 = fmaf(w, q.y, a1);
        a2 = fmaf(w, q.z, a2); a3 = fmaf(w, q.w, a3);
    }
    {   // self loop
        const float4 q = *(const float4*)&in[(size_t)v * C_IN + off];
        a0 = fmaf(dv, q.x, a0); a1 = fmaf(dv, q.y, a1);
        a2 = fmaf(dv, q.z, a2); a3 = fmaf(dv, q.w, a3);
    }
    *(float4*)&out[(size_t)v * C_IN + off] =
        make_float4(dv * a0, dv * a1, dv * a2, dv * a3);
}

// ---------------- BN stats for layer 2 (streaming pass over d_h2) ------------
__global__ __launch_bounds__(256) void k_bnstats2() {
    float s = 0.f, q = 0.f;
    for (int r = blockIdx.x; r < N_NODES; r += gridDim.x) {
        const float v = d_h2[(size_t)r * C_IN + threadIdx.x];
        s += v; q = fmaf(v, v, q);
    }
    atomicAdd(&d_sum[threadIdx.x], s);
    atomicAdd(&d_sum[C_IN + threadIdx.x], q);
}

// ---------------- Tensor-core NT GEMM (bf16-split, fp32-quality) -------------
// C[M,N] = A[M,K] * B[N,K]^T.  Block 128x128, BK=32, 8 warps (2x4), warp 64x32.
// D += Ah*Bh + Ah*Bl + Al*Bh.
// LAYER 1: A = d_agx, C = d_h1, fused BN-stats atomics into d_sum.
// LAYER 2: A = d_h1 (+fused relu(a*v+b) on load), C = d_xl2.
template <int K, int LAYER>
__global__ __launch_bounds__(256) void k_gemm(const float* __restrict__ B,
                                              int M, int Ncols)
{
    const float* __restrict__ A = (LAYER == 1) ? d_agx : d_h1;
    float* __restrict__ Cm = (LAYER == 1) ? d_h1 : d_xl2;

    constexpr int BK  = 32;
    constexpr int LDS = 40;                    // halves per smem row (80B stride)
    __shared__ __nv_bfloat16 sAh[128 * LDS];
    __shared__ __nv_bfloat16 sAl[128 * LDS];
    __shared__ __nv_bfloat16 sBh[128 * LDS];
    __shared__ __nv_bfloat16 sBl[128 * LDS];

    const int bm = blockIdx.y * 128, bn = blockIdx.x * 128;
    const int tid = threadIdx.x;
    const int lane = tid & 31, wid = tid >> 5;
    const int mw = wid >> 2, nw = wid & 3;     // warp grid 2(m) x 4(n)

    float acc[4][4][4];
#pragma unroll
    for (int i = 0; i < 4; i++)
#pragma unroll
        for (int j = 0; j < 4; j++)
#pragma unroll
            for (int q = 0; q < 4; q++) acc[i][j][q] = 0.f;

    const int grow = tid >> 1;                 // 0..127
    const int gk   = (tid & 1) * 16;           // 0 or 16

    float4 ra[4], rb[4];
    auto gload = [&](int k0) {
        const int arow = bm + grow;
        if (arow < M) {
#pragma unroll
            for (int i = 0; i < 4; i++)
                ra[i] = *(const float4*)&A[(size_t)arow * K + k0 + gk + i * 4];
        } else {
#pragma unroll
            for (int i = 0; i < 4; i++) ra[i] = make_float4(0.f, 0.f, 0.f, 0.f);
        }
        if (LAYER == 2) {
#pragma unroll
            for (int i = 0; i < 4; i++) {
                const int kb = k0 + gk + i * 4;
                const float4 s4 = *(const float4*)&d_ab[kb];
                const float4 t4 = *(const float4*)&d_ab[C_MID + kb];
                ra[i].x = fmaxf(fmaf(ra[i].x, s4.x, t4.x), 0.f);
                ra[i].y = fmaxf(fmaf(ra[i].y, s4.y, t4.y), 0.f);
                ra[i].z = fmaxf(fmaf(ra[i].z, s4.z, t4.z), 0.f);
                ra[i].w = fmaxf(fmaf(ra[i].w, s4.w, t4.w), 0.f);
            }
        }
        const int brow = bn + grow;
#pragma unroll
        for (int i = 0; i < 4; i++)
            rb[i] = *(const float4*)&B[(size_t)brow * K + k0 + gk + i * 4];
    };

    auto sstore = [&]() {
        const int base = grow * LDS + gk;
#pragma unroll
        for (int i = 0; i < 4; i++) {
            __nv_bfloat16 h0, l0, h1, l1, h2, l2, h3, l3;
            bfsplit(ra[i].x, h0, l0); bfsplit(ra[i].y, h1, l1);
            bfsplit(ra[i].z, h2, l2); bfsplit(ra[i].w, h3, l3);
            *(uint2*)&sAh[base + i * 4] = make_uint2(pkbf(h0, h1), pkbf(h2, h3));
            *(uint2*)&sAl[base + i * 4] = make_uint2(pkbf(l0, l1), pkbf(l2, l3));
            bfsplit(rb[i].x, h0, l0); bfsplit(rb[i].y, h1, l1);
            bfsplit(rb[i].z, h2, l2); bfsplit(rb[i].w, h3, l3);
            *(uint2*)&sBh[base + i * 4] = make_uint2(pkbf(h0, h1), pkbf(h2, h3));
            *(uint2*)&sBl[base + i * 4] = make_uint2(pkbf(l0, l1), pkbf(l2, l3));
        }
    };

    const uint32_t uAh = s2u(sAh), uAl = s2u(sAl);
    const uint32_t uBh = s2u(sBh), uBl = s2u(sBl);

    gload(0);
    constexpr int NT = K / BK;
#pragma unroll 1
    for (int kt = 0; kt < NT; kt++) {
        __syncthreads();
        sstore();
        __syncthreads();
        if (kt + 1 < NT) gload((kt + 1) * BK);

#pragma unroll
        for (int ks = 0; ks < 2; ks++) {
            const int koff = ks * 16 + ((lane & 16) ? 8 : 0);
            uint32_t Bh0[8], Bl0[8];
#pragma unroll
            for (int nf2 = 0; nf2 < 2; nf2++) {
                const int row = nw * 32 + nf2 * 16 + (lane & 15);
                const uint32_t ad = (uint32_t)(row * LDS + koff) * 2;
                ldm_x4(Bh0[nf2*4+0], Bh0[nf2*4+1], Bh0[nf2*4+2], Bh0[nf2*4+3], uBh + ad);
                ldm_x4(Bl0[nf2*4+0], Bl0[nf2*4+1], Bl0[nf2*4+2], Bl0[nf2*4+3], uBl + ad);
            }
#pragma unroll
            for (int mf = 0; mf < 4; mf++) {
                const int arow = mw * 64 + mf * 16 + (lane & 15);
                const uint32_t ad = (uint32_t)(arow * LDS + koff) * 2;
                uint32_t Ah[4], Al[4];
                ldm_x4(Ah[0], Ah[1], Ah[2], Ah[3], uAh + ad);
                ldm_x4(Al[0], Al[1], Al[2], Al[3], uAl + ad);
#pragma unroll
                for (int nf = 0; nf < 4; nf++) {
                    const int b = (nf >> 1) * 4 + (nf & 1);
                    const uint32_t bh0 = Bh0[b], bh1 = Bh0[b + 2];
                    const uint32_t bl0 = Bl0[b], bl1 = Bl0[b + 2];
                    mma_bf16(acc[mf][nf], Ah, bh0, bh1);
                    mma_bf16(acc[mf][nf], Ah, bl0, bl1);
                    mma_bf16(acc[mf][nf], Al, bh0, bh1);
                }
            }
        }
    }

    // epilogue: store C (+ fused BN stats for LAYER 1)
#pragma unroll
    for (int mf = 0; mf < 4; mf++) {
        const int r0 = bm + mw * 64 + mf * 16 + (lane >> 2);
        const int r1 = r0 + 8;
#pragma unroll
        for (int nf = 0; nf < 4; nf++) {
            const int col = bn + nw * 32 + nf * 8 + (lane & 3) * 2;
            if (r0 < M)
                *(float2*)&Cm[(size_t)r0 * Ncols + col] =
                    make_float2(acc[mf][nf][0], acc[mf][nf][1]);
            if (r1 < M)
                *(float2*)&Cm[(size_t)r1 * Ncols + col] =
                    make_float2(acc[mf][nf][2], acc[mf][nf][3]);
        }
    }
    if (LAYER == 1) {
        // per-thread partial sums over its 8 columns (rows >= M contribute 0)
        float s[8], q[8];
#pragma unroll
        for (int c = 0; c < 8; c++) { s[c] = 0.f; q[c] = 0.f; }
#pragma unroll
        for (int mf = 0; mf < 4; mf++)
#pragma unroll
            for (int nf = 0; nf < 4; nf++)
#pragma unroll
                for (int pair = 0; pair < 2; pair++) {
                    const int c = nf * 2 + pair;
                    const float v0 = acc[mf][nf][pair];       // row r0
                    const float v1 = acc[mf][nf][2 + pair];   // row r1
                    s[c] += v0 + v1;
                    q[c] = fmaf(v0, v0, q[c]);
                    q[c] = fmaf(v1, v1, q[c]);
                }
        // reduce across the 8 row-lane groups (lane>>2)
#pragma unroll
        for (int off = 4; off < 32; off <<= 1)
#pragma unroll
            for (int c = 0; c < 8; c++) {
                s[c] += __shfl_xor_sync(0xffffffffu, s[c], off);
                q[c] += __shfl_xor_sync(0xffffffffu, q[c], off);
            }
        if (lane < 4) {
#pragma unroll
            for (int c = 0; c < 8; c++) {
                const int col = bn + nw * 32 + (c >> 1) * 8 + lane * 2 + (c & 1);
                atomicAdd(&d_sum[col], s[c]);
                atomicAdd(&d_sum[C_MID + col], q[c]);
            }
        }
    }
}

// ---------------- BN finalize (also restores d_sum==0 invariant) -------------
__global__ void k_bnfinal(const float* __restrict__ g, const float* __restrict__ be, int F) {
    const int f = threadIdx.x + blockIdx.x * blockDim.x;
    if (f >= F) return;
    const float invN = 1.f / (float)N_NODES;
    const float s = d_sum[f], q = d_sum[F + f];
    const float m = s * invN;
    const float var = q * invN - m * m;
    const float a = g[f] * rsqrtf(var + 1e-5f);
    d_ab[f] = a;
    d_ab[F + f] = be[f] - m * a;
    d_sum[f] = 0.f;
    d_sum[F + f] = 0.f;
}

// ---------------- final: out = relu(a2*h2 + b2 + x) ----------------
__global__ __launch_bounds__(256) void k_final(const float* __restrict__ x,
                                               float* __restrict__ out) {
    const int idx = blockIdx.x * 256 + threadIdx.x;
    const int f = threadIdx.x;
    const float v = fmaf(d_ab[f], d_h2[idx], d_ab[C_IN + f]) + x[idx];
    out[idx] = fmaxf(v, 0.f);
}

// ---------------- launcher (kernel launches ONLY — graph-capture safe) --------
extern "C" void kernel_launch(void* const* d_in, const int* in_sizes, int n_in,
                              void* d_out, int out_size) {
    (void)in_sizes; (void)n_in; (void)out_size;
    const float* x  = (const float*)d_in[0];
    const int*   es = (const int*)d_in[1];      // int32 edge list [2, E]
    const float* W1 = (const float*)d_in[2];
    const float* g1 = (const float*)d_in[3];
    const float* b1 = (const float*)d_in[4];
    const float* W2 = (const float*)d_in[5];
    const float* g2 = (const float*)d_in[6];
    const float* b2 = (const float*)d_in[7];
    float* out = (float*)d_out;

    // graph structure (d_cnt==0 invariant on entry)
    k_count<<<(E_EDGES + 255) / 256, 256>>>(es);
    k_scan<<<1, 1024>>>();
    k_fill<<<(E_EDGES + 255) / 256, 256>>>(es);

    // layer 1: aggregate x -> TC GEMM (+BN stats fused) -> BN finalize
    k_agg<1><<<(N_NODES + 1) / 2, 128>>>(x);
    {
        dim3 grid(C_MID / 128, (N_NODES + 127) / 128);   // (4, 79)
        k_gemm<C_IN, 1><<<grid, 256>>>(W1, N_NODES, C_MID);
    }
    k_bnfinal<<<1, C_MID>>>(g1, b1, C_MID);

    // layer 2: (BN+ReLU fused) TC GEMM -> aggregate -> BN stats -> BN -> out
    {
        dim3 grid(C_IN / 128, (N_NODES + 127) / 128);    // (2, 79)
        k_gemm<C_MID, 2><<<grid, 256>>>(W2, N_NODES, C_IN);
    }
    k_agg<2><<<(N_NODES + 1) / 2, 128>>>(nullptr);
    k_bnstats2<<<296, 256>>>();
    k_bnfinal<<<1, C_IN>>>(g2, b2, C_IN);
    k_final<<<N_NODES, 256>>>(x, out);
}

// round 13
// speedup vs baseline: 1.9030x; 1.0131x over previous
#include <cuda_runtime.h>
#include <cuda_bf16.h>
#include <cuda_fp16.h>
#include <math.h>
#include <stdint.h>

#define N_NODES 10000
#define E_EDGES 160000
#define C_IN    256
#define C_MID   512

// ---------------- scratch (static __device__ allocations only) ----------------
// Invariants across calls (zero at module load, restored every call):
//   d_cnt == 0   (re-zeroed by k_fill after its readers ran)
//   d_sum == 0   (reset by k_bnfinal after consumption)
__device__ __half d_xh [(size_t)N_NODES * C_IN];   // fp16 copy of x (gather operand)
__device__ float d_agx[(size_t)N_NODES * C_IN];    // Â x           (256-wide)
__device__ float d_h1 [(size_t)N_NODES * C_MID];   // (Âx) W1^T     (pre-BN)
__device__ __half d_xl2h[(size_t)N_NODES * C_IN];  // h1n W2^T (fp16 gather operand)
__device__ float d_h2 [(size_t)N_NODES * C_IN];    // Â xl2         (pre-BN)
__device__ int   d_cnt[N_NODES];
__device__ int   d_off[N_NODES + 1];
__device__ int   d_cur[N_NODES];
__device__ float d_dis[N_NODES];                   // deg^-0.5 (incl self loop)
__device__ int   d_esrc[E_EDGES];                  // CSR-by-dst source rows
__device__ float d_sum[2 * C_MID];                 // BN sums: [0..F)=sum, [F..2F)=sumsq
__device__ float d_ab [2 * C_MID];                 // BN affine: [0..F)=a, [F..2F)=b

// ---------------- helpers ----------------
__device__ __forceinline__ uint32_t s2u(const void* p) {
    return (uint32_t)__cvta_generic_to_shared(p);
}
__device__ __forceinline__ void bfsplit(float x, __nv_bfloat16& h, __nv_bfloat16& l) {
    h = __float2bfloat16(x);
    l = __float2bfloat16(x - __bfloat162float(h));
}
__device__ __forceinline__ uint32_t pkbf(__nv_bfloat16 a, __nv_bfloat16 b) {
    __nv_bfloat162 v; v.x = a; v.y = b;
    return *(uint32_t*)&v;
}
__device__ __forceinline__ void ldm_x4(uint32_t& r0, uint32_t& r1, uint32_t& r2,
                                       uint32_t& r3, uint32_t addr) {
    asm volatile("ldmatrix.sync.aligned.m8n8.x4.shared.b16 {%0,%1,%2,%3}, [%4];"
                 : "=r"(r0), "=r"(r1), "=r"(r2), "=r"(r3) : "r"(addr));
}
__device__ __forceinline__ void mma_bf16(float* d, const uint32_t* a,
                                         uint32_t b0, uint32_t b1) {
    asm volatile(
        "mma.sync.aligned.m16n8k16.row.col.f32.bf16.bf16.f32 "
        "{%0,%1,%2,%3}, {%4,%5,%6,%7}, {%8,%9}, {%0,%1,%2,%3};"
        : "+f"(d[0]), "+f"(d[1]), "+f"(d[2]), "+f"(d[3])
        : "r"(a[0]), "r"(a[1]), "r"(a[2]), "r"(a[3]), "r"(b0), "r"(b1));
}
// load 4 consecutive halfs as 2x half2, return float4
__device__ __forceinline__ float4 ldh4(const __half* p) {
    const uint2 u = *(const uint2*)p;
    const float2 lo = __half22float2(*(const __half2*)&u.x);
    const float2 hi = __half22float2(*(const __half2*)&u.y);
    return make_float4(lo.x, lo.y, hi.x, hi.y);
}

// ---------------- x -> fp16 conversion ----------------
__global__ __launch_bounds__(256) void k_half(const float* __restrict__ x) {
    const int i = (blockIdx.x * 256 + threadIdx.x) * 4;   // N*C_IN mult of 1024
    const float4 v = *(const float4*)&x[i];
    uint2 u;
    *(__half2*)&u.x = __floats2half2_rn(v.x, v.y);
    *(__half2*)&u.y = __floats2half2_rn(v.z, v.w);
    *(uint2*)&d_xh[i] = u;
}

// ---------------- degree count (in-degree over col); d_cnt==0 on entry -------
__global__ void k_count(const int* __restrict__ es) {
    int e = blockIdx.x * blockDim.x + threadIdx.x;
    if (e < E_EDGES) {
        unsigned c = (unsigned)es[E_EDGES + e];
        if (c < N_NODES) atomicAdd(&d_cnt[c], 1);
    }
}

// ---------------- exclusive scan (single block) + dis ----------------
__global__ void k_scan() {
    __shared__ int sh[1024];
    int t = threadIdx.x;
    const int CH = (N_NODES + 1023) / 1024;  // 10
    int base = t * CH;
    int loc = 0;
    for (int i = 0; i < CH; i++) {
        int idx = base + i;
        if (idx < N_NODES) loc += d_cnt[idx];
    }
    sh[t] = loc;
    __syncthreads();
    for (int s = 1; s < 1024; s <<= 1) {
        int v = (t >= s) ? sh[t - s] : 0;
        __syncthreads();
        sh[t] += v;
        __syncthreads();
    }
    int run = (t == 0) ? 0 : sh[t - 1];
    for (int i = 0; i < CH; i++) {
        int idx = base + i;
        if (idx < N_NODES) {
            d_off[idx] = run;
            d_cur[idx] = run;
            int c = d_cnt[idx];
            d_dis[idx] = rsqrtf((float)(c + 1));   // +1 self loop; always > 0
            run += c;
        }
    }
    if (t == 1023) d_off[N_NODES] = sh[1023];
}

// ---------------- CSR fill + restore d_cnt==0 for next call ----------------
__global__ void k_fill(const int* __restrict__ es) {
    int e = blockIdx.x * blockDim.x + threadIdx.x;
    if (e < N_NODES) d_cnt[e] = 0;     // readers (count/scan) already ran
    if (e < E_EDGES) {
        unsigned r = (unsigned)es[e];
        unsigned c = (unsigned)es[E_EDGES + e];
        if (r < N_NODES && c < N_NODES) {
            int p = atomicAdd(&d_cur[c], 1);
            d_esrc[p] = (int)r;
        }
    }
}

// ---------------- CSR gather (fp16 rows, fp32 accum; 2 nodes/block) ----------
// MODE 1: in = d_xh,   out = d_agx.   MODE 2: in = d_xl2h, out = d_h2.
template <int MODE>
__global__ __launch_bounds__(128) void k_agg() {
    const __half* __restrict__ in = (MODE == 1) ? d_xh : d_xl2h;
    float* __restrict__ out = (MODE == 1) ? d_agx : d_h2;

    const int v = blockIdx.x * 2 + (threadIdx.x >> 6);   // 64 threads per node
    const int off = (threadIdx.x & 63) * 4;
    if (v >= N_NODES) return;

    float a0 = 0.f, a1 = 0.f, a2 = 0.f, a3 = 0.f;
    const int beg = d_off[v], end = d_off[v + 1];
    const float dv = d_dis[v];

    int e = beg;
    for (; e + 3 < end; e += 4) {
        const int s0 = d_esrc[e + 0], s1 = d_esrc[e + 1];
        const int s2 = d_esrc[e + 2], s3 = d_esrc[e + 3];
        const float w0 = d_dis[s0], w1 = d_dis[s1];
        const float w2 = d_dis[s2], w3 = d_dis[s3];
        const float4 q0 = ldh4(&in[(size_t)s0 * C_IN + off]);
        const float4 q1 = ldh4(&in[(size_t)s1 * C_IN + off]);
        const float4 q2 = ldh4(&in[(size_t)s2 * C_IN + off]);
        const float4 q3 = ldh4(&in[(size_t)s3 * C_IN + off]);
        a0 = fmaf(w0, q0.x, a0); a1 = fmaf(w0, q0.y, a1);
        a2 = fmaf(w0, q0.z, a2); a3 = fmaf(w0, q0.w, a3);
        a0 = fmaf(w1, q1.x, a0); a1 = fmaf(w1, q1.y, a1);
        a2 = fmaf(w1, q1.z, a2); a3 = fmaf(w1, q1.w, a3);
        a0 = fmaf(w2, q2.x, a0); a1 = fmaf(w2, q2.y, a1);
        a2 = fmaf(w2, q2.z, a2); a3 = fmaf(w2, q2.w, a3);
        a0 = fmaf(w3, q3.x, a0); a1 = fmaf(w3, q3.y, a1);
        a2 = fmaf(w3, q3.z, a2); a3 = fmaf(w3, q3.w, a3);
    }
    for (; e < end; e++) {
        const int s = d_esrc[e];
        const float w = d_dis[s];
        const float4 q = ldh4(&in[(size_t)s * C_IN + off]);
        a0 = fmaf(w, q.x, a0); a1 = fmaf(w, q.y, a1);
        a2 = fmaf(w, q.z, a2); a3 = fmaf(w, q.w, a3);
    }
    {   // self loop
        const float4 q = ldh4(&in[(size_t)v * C_IN + off]);
        a0 = fmaf(dv, q.x, a0); a1 = fmaf(dv, q.y, a1);
        a2 = fmaf(dv, q.z, a2); a3 = fmaf(dv, q.w, a3);
    }
    *(float4*)&out[(size_t)v * C_IN + off] =
        make_float4(dv * a0, dv * a1, dv * a2, dv * a3);
}

// ---------------- BN stats for layer 2 (streaming pass over d_h2) ------------
__global__ __launch_bounds__(256) void k_bnstats2() {
    float s = 0.f, q = 0.f;
    for (int r = blockIdx.x; r < N_NODES; r += gridDim.x) {
        const float v = d_h2[(size_t)r * C_IN + threadIdx.x];
        s += v; q = fmaf(v, v, q);
    }
    atomicAdd(&d_sum[threadIdx.x], s);
    atomicAdd(&d_sum[C_IN + threadIdx.x], q);
}

// ---------------- Tensor-core NT GEMM (bf16-split, fp32-quality) -------------
// C[M,N] = A[M,K] * B[N,K]^T.  Block 128x128, BK=32, 8 warps (2x4), warp 64x32.
// D += Ah*Bh + Ah*Bl + Al*Bh.
// LAYER 1: A = d_agx, C = d_h1 (fp32), fused BN-stats atomics into d_sum.
// LAYER 2: A = d_h1 (+fused relu(a*v+b) on load), C = d_xl2h (fp16).
template <int K, int LAYER>
__global__ __launch_bounds__(256) void k_gemm(const float* __restrict__ B,
                                              int M, int Ncols)
{
    const float* __restrict__ A = (LAYER == 1) ? d_agx : d_h1;

    constexpr int BK  = 32;
    constexpr int LDS = 40;                    // halves per smem row (80B stride)
    __shared__ __nv_bfloat16 sAh[128 * LDS];
    __shared__ __nv_bfloat16 sAl[128 * LDS];
    __shared__ __nv_bfloat16 sBh[128 * LDS];
    __shared__ __nv_bfloat16 sBl[128 * LDS];

    const int bm = blockIdx.y * 128, bn = blockIdx.x * 128;
    const int tid = threadIdx.x;
    const int lane = tid & 31, wid = tid >> 5;
    const int mw = wid >> 2, nw = wid & 3;     // warp grid 2(m) x 4(n)

    float acc[4][4][4];
#pragma unroll
    for (int i = 0; i < 4; i++)
#pragma unroll
        for (int j = 0; j < 4; j++)
#pragma unroll
            for (int q = 0; q < 4; q++) acc[i][j][q] = 0.f;

    const int grow = tid >> 1;                 // 0..127
    const int gk   = (tid & 1) * 16;           // 0 or 16

    float4 ra[4], rb[4];
    auto gload = [&](int k0) {
        const int arow = bm + grow;
        if (arow < M) {
#pragma unroll
            for (int i = 0; i < 4; i++)
                ra[i] = *(const float4*)&A[(size_t)arow * K + k0 + gk + i * 4];
        } else {
#pragma unroll
            for (int i = 0; i < 4; i++) ra[i] = make_float4(0.f, 0.f, 0.f, 0.f);
        }
        if (LAYER == 2) {
#pragma unroll
            for (int i = 0; i < 4; i++) {
                const int kb = k0 + gk + i * 4;
                const float4 s4 = *(const float4*)&d_ab[kb];
                const float4 t4 = *(const float4*)&d_ab[C_MID + kb];
                ra[i].x = fmaxf(fmaf(ra[i].x, s4.x, t4.x), 0.f);
                ra[i].y = fmaxf(fmaf(ra[i].y, s4.y, t4.y), 0.f);
                ra[i].z = fmaxf(fmaf(ra[i].z, s4.z, t4.z), 0.f);
                ra[i].w = fmaxf(fmaf(ra[i].w, s4.w, t4.w), 0.f);
            }
        }
        const int brow = bn + grow;
#pragma unroll
        for (int i = 0; i < 4; i++)
            rb[i] = *(const float4*)&B[(size_t)brow * K + k0 + gk + i * 4];
    };

    auto sstore = [&]() {
        const int base = grow * LDS + gk;
#pragma unroll
        for (int i = 0; i < 4; i++) {
            __nv_bfloat16 h0, l0, h1, l1, h2, l2, h3, l3;
            bfsplit(ra[i].x, h0, l0); bfsplit(ra[i].y, h1, l1);
            bfsplit(ra[i].z, h2, l2); bfsplit(ra[i].w, h3, l3);
            *(uint2*)&sAh[base + i * 4] = make_uint2(pkbf(h0, h1), pkbf(h2, h3));
            *(uint2*)&sAl[base + i * 4] = make_uint2(pkbf(l0, l1), pkbf(l2, l3));
            bfsplit(rb[i].x, h0, l0); bfsplit(rb[i].y, h1, l1);
            bfsplit(rb[i].z, h2, l2); bfsplit(rb[i].w, h3, l3);
            *(uint2*)&sBh[base + i * 4] = make_uint2(pkbf(h0, h1), pkbf(h2, h3));
            *(uint2*)&sBl[base + i * 4] = make_uint2(pkbf(l0, l1), pkbf(l2, l3));
        }
    };

    const uint32_t uAh = s2u(sAh), uAl = s2u(sAl);
    const uint32_t uBh = s2u(sBh), uBl = s2u(sBl);

    gload(0);
    constexpr int NT = K / BK;
#pragma unroll 1
    for (int kt = 0; kt < NT; kt++) {
        __syncthreads();
        sstore();
        __syncthreads();
        if (kt + 1 < NT) gload((kt + 1) * BK);

#pragma unroll
        for (int ks = 0; ks < 2; ks++) {
            const int koff = ks * 16 + ((lane & 16) ? 8 : 0);
            uint32_t Bh0[8], Bl0[8];
#pragma unroll
            for (int nf2 = 0; nf2 < 2; nf2++) {
                const int row = nw * 32 + nf2 * 16 + (lane & 15);
                const uint32_t ad = (uint32_t)(row * LDS + koff) * 2;
                ldm_x4(Bh0[nf2*4+0], Bh0[nf2*4+1], Bh0[nf2*4+2], Bh0[nf2*4+3], uBh + ad);
                ldm_x4(Bl0[nf2*4+0], Bl0[nf2*4+1], Bl0[nf2*4+2], Bl0[nf2*4+3], uBl + ad);
            }
#pragma unroll
            for (int mf = 0; mf < 4; mf++) {
                const int arow = mw * 64 + mf * 16 + (lane & 15);
                const uint32_t ad = (uint32_t)(arow * LDS + koff) * 2;
                uint32_t Ah[4], Al[4];
                ldm_x4(Ah[0], Ah[1], Ah[2], Ah[3], uAh + ad);
                ldm_x4(Al[0], Al[1], Al[2], Al[3], uAl + ad);
#pragma unroll
                for (int nf = 0; nf < 4; nf++) {
                    const int b = (nf >> 1) * 4 + (nf & 1);
                    const uint32_t bh0 = Bh0[b], bh1 = Bh0[b + 2];
                    const uint32_t bl0 = Bl0[b], bl1 = Bl0[b + 2];
                    mma_bf16(acc[mf][nf], Ah, bh0, bh1);
                    mma_bf16(acc[mf][nf], Ah, bl0, bl1);
                    mma_bf16(acc[mf][nf], Al, bh0, bh1);
                }
            }
        }
    }

    // epilogue: LAYER 1 -> fp32 store + fused BN stats; LAYER 2 -> fp16 store
#pragma unroll
    for (int mf = 0; mf < 4; mf++) {
        const int r0 = bm + mw * 64 + mf * 16 + (lane >> 2);
        const int r1 = r0 + 8;
#pragma unroll
        for (int nf = 0; nf < 4; nf++) {
            const int col = bn + nw * 32 + nf * 8 + (lane & 3) * 2;
            if (LAYER == 1) {
                if (r0 < M)
                    *(float2*)&d_h1[(size_t)r0 * Ncols + col] =
                        make_float2(acc[mf][nf][0], acc[mf][nf][1]);
                if (r1 < M)
                    *(float2*)&d_h1[(size_t)r1 * Ncols + col] =
                        make_float2(acc[mf][nf][2], acc[mf][nf][3]);
            } else {
                if (r0 < M)
                    *(__half2*)&d_xl2h[(size_t)r0 * Ncols + col] =
                        __floats2half2_rn(acc[mf][nf][0], acc[mf][nf][1]);
                if (r1 < M)
                    *(__half2*)&d_xl2h[(size_t)r1 * Ncols + col] =
                        __floats2half2_rn(acc[mf][nf][2], acc[mf][nf][3]);
            }
        }
    }
    if (LAYER == 1) {
        // per-thread partial sums over its 8 columns (rows >= M contribute 0)
        float s[8], q[8];
#pragma unroll
        for (int c = 0; c < 8; c++) { s[c] = 0.f; q[c] = 0.f; }
#pragma unroll
        for (int mf = 0; mf < 4; mf++)
#pragma unroll
            for (int nf = 0; nf < 4; nf++)
#pragma unroll
                for (int pair = 0; pair < 2; pair++) {
                    const int c = nf * 2 + pair;
                    const float v0 = acc[mf][nf][pair];       // row r0
                    const float v1 = acc[mf][nf][2 + pair];   // row r1
                    s[c] += v0 + v1;
                    q[c] = fmaf(v0, v0, q[c]);
                    q[c] = fmaf(v1, v1, q[c]);
                }
        // reduce across the 8 row-lane groups (lane>>2)
#pragma unroll
        for (int off = 4; off < 32; off <<= 1)
#pragma unroll
            for (int c = 0; c < 8; c++) {
                s[c] += __shfl_xor_sync(0xffffffffu, s[c], off);
                q[c] += __shfl_xor_sync(0xffffffffu, q[c], off);
            }
        if (lane < 4) {
#pragma unroll
            for (int c = 0; c < 8; c++) {
                const int col = bn + nw * 32 + (c >> 1) * 8 + lane * 2 + (c & 1);
                atomicAdd(&d_sum[col], s[c]);
                atomicAdd(&d_sum[C_MID + col], q[c]);
            }
        }
    }
}

// ---------------- BN finalize (also restores d_sum==0 invariant) -------------
__global__ void k_bnfinal(const float* __restrict__ g, const float* __restrict__ be, int F) {
    const int f = threadIdx.x + blockIdx.x * blockDim.x;
    if (f >= F) return;
    const float invN = 1.f / (float)N_NODES;
    const float s = d_sum[f], q = d_sum[F + f];
    const float m = s * invN;
    const float var = q * invN - m * m;
    const float a = g[f] * rsqrtf(var + 1e-5f);
    d_ab[f] = a;
    d_ab[F + f] = be[f] - m * a;
    d_sum[f] = 0.f;
    d_sum[F + f] = 0.f;
}

// ---------------- final: out = relu(a2*h2 + b2 + x) ----------------
__global__ __launch_bounds__(256) void k_final(const float* __restrict__ x,
                                               float* __restrict__ out) {
    const int idx = blockIdx.x * 256 + threadIdx.x;
    const int f = threadIdx.x;
    const float v = fmaf(d_ab[f], d_h2[idx], d_ab[C_IN + f]) + x[idx];
    out[idx] = fmaxf(v, 0.f);
}

// ---------------- launcher (kernel launches ONLY — graph-capture safe) --------
extern "C" void kernel_launch(void* const* d_in, const int* in_sizes, int n_in,
                              void* d_out, int out_size) {
    (void)in_sizes; (void)n_in; (void)out_size;
    const float* x  = (const float*)d_in[0];
    const int*   es = (const int*)d_in[1];      // int32 edge list [2, E]
    const float* W1 = (const float*)d_in[2];
    const float* g1 = (const float*)d_in[3];
    const float* b1 = (const float*)d_in[4];
    const float* W2 = (const float*)d_in[5];
    const float* g2 = (const float*)d_in[6];
    const float* b2 = (const float*)d_in[7];
    float* out = (float*)d_out;

    // graph structure (d_cnt==0 invariant on entry) + x -> fp16
    k_count<<<(E_EDGES + 255) / 256, 256>>>(es);
    k_scan<<<1, 1024>>>();
    k_fill<<<(E_EDGES + 255) / 256, 256>>>(es);
    k_half<<<(N_NODES * C_IN) / 1024, 256>>>(x);

    // layer 1: aggregate x (fp16 gather) -> TC GEMM (+BN stats fused) -> BN finalize
    k_agg<1><<<(N_NODES + 1) / 2, 128>>>();
    {
        dim3 grid(C_MID / 128, (N_NODES + 127) / 128);   // (4, 79)
        k_gemm<C_IN, 1><<<grid, 256>>>(W1, N_NODES, C_MID);
    }
    k_bnfinal<<<1, C_MID>>>(g1, b1, C_MID);

    // layer 2: (BN+ReLU fused) TC GEMM (fp16 out) -> aggregate -> BN stats -> BN -> out
    {
        dim3 grid(C_IN / 128, (N_NODES + 127) / 128);    // (2, 79)
        k_gemm<C_MID, 2><<<grid, 256>>>(W2, N_NODES, C_IN);
    }
    k_agg<2><<<(N_NODES + 1) / 2, 128>>>();
    k_bnstats2<<<296, 256>>>();
    k_bnfinal<<<1, C_IN>>>(g2, b2, C_IN);
    k_final<<<N_NODES, 256>>>(x, out);
}

// round 15
// speedup vs baseline: 1.9125x; 1.0050x over previous
#include <cuda_runtime.h>
#include <cuda_bf16.h>
#include <cuda_fp16.h>
#include <math.h>
#include <stdint.h>

#define N_NODES 10000
#define E_EDGES 160000
#define C_IN    256
#define C_MID   512

// ---------------- scratch (static __device__ allocations only) ----------------
// Invariant across calls: d_cnt == 0 (restored by k_fill after its readers ran).
// d_sum1/d_sum2 are reset by k_pre at the start of every call.
__device__ __half d_xh [(size_t)N_NODES * C_IN];   // fp16 copy of x (gather operand)
__device__ float d_agx[(size_t)N_NODES * C_IN];    // Â x           (256-wide)
__device__ float d_h1 [(size_t)N_NODES * C_MID];   // (Âx) W1^T     (pre-BN)
__device__ __half d_xl2h[(size_t)N_NODES * C_IN];  // h1n W2^T (fp16 gather operand)
__device__ float d_h2 [(size_t)N_NODES * C_IN];    // Â xl2         (pre-BN)
__device__ int   d_cnt[N_NODES];
__device__ int   d_off[N_NODES + 1];
__device__ int   d_cur[N_NODES];
__device__ float d_dis[N_NODES];                   // deg^-0.5 (incl self loop)
__device__ int   d_esrc[E_EDGES];                  // CSR-by-dst source rows
__device__ float d_sum1[2 * C_MID];                // layer1 BN sums (gemm1 epilogue)
__device__ float d_sum2[2 * C_IN];                 // layer2 BN sums (bnstats2)

// ---------------- helpers ----------------
__device__ __forceinline__ uint32_t s2u(const void* p) {
    return (uint32_t)__cvta_generic_to_shared(p);
}
__device__ __forceinline__ void bfsplit(float x, __nv_bfloat16& h, __nv_bfloat16& l) {
    h = __float2bfloat16(x);
    l = __float2bfloat16(x - __bfloat162float(h));
}
__device__ __forceinline__ uint32_t pkbf(__nv_bfloat16 a, __nv_bfloat16 b) {
    __nv_bfloat162 v; v.x = a; v.y = b;
    return *(uint32_t*)&v;
}
__device__ __forceinline__ void ldm_x4(uint32_t& r0, uint32_t& r1, uint32_t& r2,
                                       uint32_t& r3, uint32_t addr) {
    asm volatile("ldmatrix.sync.aligned.m8n8.x4.shared.b16 {%0,%1,%2,%3}, [%4];"
                 : "=r"(r0), "=r"(r1), "=r"(r2), "=r"(r3) : "r"(addr));
}
__device__ __forceinline__ void mma_bf16(float* d, const uint32_t* a,
                                         uint32_t b0, uint32_t b1) {
    asm volatile(
        "mma.sync.aligned.m16n8k16.row.col.f32.bf16.bf16.f32 "
        "{%0,%1,%2,%3}, {%4,%5,%6,%7}, {%8,%9}, {%0,%1,%2,%3};"
        : "+f"(d[0]), "+f"(d[1]), "+f"(d[2]), "+f"(d[3])
        : "r"(a[0]), "r"(a[1]), "r"(a[2]), "r"(a[3]), "r"(b0), "r"(b1));
}
// load 4 consecutive halfs as 2x half2, return float4
__device__ __forceinline__ float4 ldh4(const __half* p) {
    const uint2 u = *(const uint2*)p;
    const float2 lo = __half22float2(*(const __half2*)&u.x);
    const float2 hi = __half22float2(*(const __half2*)&u.y);
    return make_float4(lo.x, lo.y, hi.x, hi.y);
}

// ---------------- k_pre: x->fp16 + degree count + BN accumulator reset -------
// grid 2500x256 = 640000 threads. d_cnt==0 on entry (invariant).
__global__ __launch_bounds__(256) void k_pre(const int* __restrict__ es,
                                             const float* __restrict__ x) {
    const int t = blockIdx.x * 256 + threadIdx.x;     // 0..639999
    if (t < 2 * C_MID) d_sum1[t] = 0.f;
    else if (t < 2 * C_MID + 2 * C_IN) d_sum2[t - 2 * C_MID] = 0.f;
    {   // fp16 conversion: 4 elements per thread covers N*C_IN = 2.56M
        const float4 v = *(const float4*)&x[t * 4];
        uint2 u;
        *(__half2*)&u.x = __floats2half2_rn(v.x, v.y);
        *(__half2*)&u.y = __floats2half2_rn(v.z, v.w);
        *(uint2*)&d_xh[t * 4] = u;
    }
    if (t < E_EDGES) {
        unsigned c = (unsigned)es[E_EDGES + t];
        if (c < N_NODES) atomicAdd(&d_cnt[c], 1);
    }
}

// ---------------- exclusive scan (single block) + dis ----------------
__global__ void k_scan() {
    __shared__ int sh[1024];
    int t = threadIdx.x;
    const int CH = (N_NODES + 1023) / 1024;  // 10
    int base = t * CH;
    int loc = 0;
    for (int i = 0; i < CH; i++) {
        int idx = base + i;
        if (idx < N_NODES) loc += d_cnt[idx];
    }
    sh[t] = loc;
    __syncthreads();
    for (int s = 1; s < 1024; s <<= 1) {
        int v = (t >= s) ? sh[t - s] : 0;
        __syncthreads();
        sh[t] += v;
        __syncthreads();
    }
    int run = (t == 0) ? 0 : sh[t - 1];
    for (int i = 0; i < CH; i++) {
        int idx = base + i;
        if (idx < N_NODES) {
            d_off[idx] = run;
            d_cur[idx] = run;
            int c = d_cnt[idx];
            d_dis[idx] = rsqrtf((float)(c + 1));   // +1 self loop; always > 0
            run += c;
        }
    }
    if (t == 1023) d_off[N_NODES] = sh[1023];
}

// ---------------- CSR fill + restore d_cnt==0 for next call ----------------
__global__ void k_fill(const int* __restrict__ es) {
    int e = blockIdx.x * blockDim.x + threadIdx.x;
    if (e < N_NODES) d_cnt[e] = 0;     // readers (pre/scan) already ran
    if (e < E_EDGES) {
        unsigned r = (unsigned)es[e];
        unsigned c = (unsigned)es[E_EDGES + e];
        if (r < N_NODES && c < N_NODES) {
            int p = atomicAdd(&d_cur[c], 1);
            d_esrc[p] = (int)r;
        }
    }
}

// ---------------- CSR gather (fp16 rows, fp32 accum; 2 nodes/block) ----------
// MODE 1: in = d_xh,   out = d_agx.   MODE 2: in = d_xl2h, out = d_h2.
template <int MODE>
__global__ __launch_bounds__(128) void k_agg() {
    const __half* __restrict__ in = (MODE == 1) ? d_xh : d_xl2h;
    float* __restrict__ out = (MODE == 1) ? d_agx : d_h2;

    const int v = blockIdx.x * 2 + (threadIdx.x >> 6);   // 64 threads per node
    const int off = (threadIdx.x & 63) * 4;
    if (v >= N_NODES) return;

    float a0 = 0.f, a1 = 0.f, a2 = 0.f, a3 = 0.f;
    const int beg = d_off[v], end = d_off[v + 1];
    const float dv = d_dis[v];

    int e = beg;
    for (; e + 3 < end; e += 4) {
        const int s0 = d_esrc[e + 0], s1 = d_esrc[e + 1];
        const int s2 = d_esrc[e + 2], s3 = d_esrc[e + 3];
        const float w0 = d_dis[s0], w1 = d_dis[s1];
        const float w2 = d_dis[s2], w3 = d_dis[s3];
        const float4 q0 = ldh4(&in[(size_t)s0 * C_IN + off]);
        const float4 q1 = ldh4(&in[(size_t)s1 * C_IN + off]);
        const float4 q2 = ldh4(&in[(size_t)s2 * C_IN + off]);
        const float4 q3 = ldh4(&in[(size_t)s3 * C_IN + off]);
        a0 = fmaf(w0, q0.x, a0); a1 = fmaf(w0, q0.y, a1);
        a2 = fmaf(w0, q0.z, a2); a3 = fmaf(w0, q0.w, a3);
        a0 = fmaf(w1, q1.x, a0); a1 = fmaf(w1, q1.y, a1);
        a2 = fmaf(w1, q1.z, a2); a3 = fmaf(w1, q1.w, a3);
        a0 = fmaf(w2, q2.x, a0); a1 = fmaf(w2, q2.y, a1);
        a2 = fmaf(w2, q2.z, a2); a3 = fmaf(w2, q2.w, a3);
        a0 = fmaf(w3, q3.x, a0); a1 = fmaf(w3, q3.y, a1);
        a2 = fmaf(w3, q3.z, a2); a3 = fmaf(w3, q3.w, a3);
    }
    for (; e < end; e++) {
        const int s = d_esrc[e];
        const float w = d_dis[s];
        const float4 q = ldh4(&in[(size_t)s * C_IN + off]);
        a0 = fmaf(w, q.x, a0); a1 = fmaf(w, q.y, a1);
        a2 = fmaf(w, q.z, a2); a3 = fmaf(w, q.w, a3);
    }
    {   // self loop
        const float4 q = ldh4(&in[(size_t)v * C_IN + off]);
        a0 = fmaf(dv, q.x, a0); a1 = fmaf(dv, q.y, a1);
        a2 = fmaf(dv, q.z, a2); a3 = fmaf(dv, q.w, a3);
    }
    *(float4*)&out[(size_t)v * C_IN + off] =
        make_float4(dv * a0, dv * a1, dv * a2, dv * a3);
}

// ---------------- BN stats for layer 2 (streaming pass over d_h2) ------------
__global__ __launch_bounds__(256) void k_bnstats2() {
    float s = 0.f, q = 0.f;
    for (int r = blockIdx.x; r < N_NODES; r += gridDim.x) {
        const float v = d_h2[(size_t)r * C_IN + threadIdx.x];
        s += v; q = fmaf(v, v, q);
    }
    atomicAdd(&d_sum2[threadIdx.x], s);
    atomicAdd(&d_sum2[C_IN + threadIdx.x], q);
}

// ---------------- Tensor-core NT GEMM (bf16-split, fp32-quality) -------------
// C[M,N] = A[M,K] * B[N,K]^T.  Block 128x128, BK=32, 8 warps (2x4), warp 64x32.
// D += Ah*Bh + Ah*Bl + Al*Bh.
// LAYER 1: A = d_agx, C = d_h1 (fp32), fused BN-stats atomics into d_sum1.
// LAYER 2: A = d_h1, BN affine computed in-block from d_sum1/g/be, fused
//          relu(a*v+b) on A-load, C = d_xl2h (fp16).
template <int K, int LAYER>
__global__ __launch_bounds__(256) void k_gemm(const float* __restrict__ B,
                                              int M, int Ncols,
                                              const float* __restrict__ g,
                                              const float* __restrict__ be)
{
    const float* __restrict__ A = (LAYER == 1) ? d_agx : d_h1;

    constexpr int BK  = 32;
    constexpr int LDS = 40;                    // halves per smem row (80B stride)
    __shared__ __nv_bfloat16 sAh[128 * LDS];
    __shared__ __nv_bfloat16 sAl[128 * LDS];
    __shared__ __nv_bfloat16 sBh[128 * LDS];
    __shared__ __nv_bfloat16 sBl[128 * LDS];
    __shared__ float sA_[C_MID], sB_[C_MID];   // BN affine (LAYER 2)

    const int bm = blockIdx.y * 128, bn = blockIdx.x * 128;
    const int tid = threadIdx.x;
    const int lane = tid & 31, wid = tid >> 5;
    const int mw = wid >> 2, nw = wid & 3;     // warp grid 2(m) x 4(n)

    if (LAYER == 2) {
        const float invN = 1.f / (float)N_NODES;
#pragma unroll
        for (int f = tid; f < K; f += 256) {
            const float s = d_sum1[f], q = d_sum1[K + f];
            const float m = s * invN;
            const float a = g[f] * rsqrtf(q * invN - m * m + 1e-5f);
            sA_[f] = a;
            sB_[f] = be[f] - m * a;
        }
        __syncthreads();
    }

    float acc[4][4][4];
#pragma unroll
    for (int i = 0; i < 4; i++)
#pragma unroll
        for (int j = 0; j < 4; j++)
#pragma unroll
            for (int q = 0; q < 4; q++) acc[i][j][q] = 0.f;

    const int grow = tid >> 1;                 // 0..127
    const int gk   = (tid & 1) * 16;           // 0 or 16

    float4 ra[4], rb[4];
    auto gload = [&](int k0) {
        const int arow = bm + grow;
        if (arow < M) {
#pragma unroll
            for (int i = 0; i < 4; i++)
                ra[i] = *(const float4*)&A[(size_t)arow * K + k0 + gk + i * 4];
        } else {
#pragma unroll
            for (int i = 0; i < 4; i++) ra[i] = make_float4(0.f, 0.f, 0.f, 0.f);
        }
        if (LAYER == 2) {
#pragma unroll
            for (int i = 0; i < 4; i++) {
                const int kb = k0 + gk + i * 4;
                const float4 s4 = *(const float4*)&sA_[kb];
                const float4 t4 = *(const float4*)&sB_[kb];
                ra[i].x = fmaxf(fmaf(ra[i].x, s4.x, t4.x), 0.f);
                ra[i].y = fmaxf(fmaf(ra[i].y, s4.y, t4.y), 0.f);
                ra[i].z = fmaxf(fmaf(ra[i].z, s4.z, t4.z), 0.f);
                ra[i].w = fmaxf(fmaf(ra[i].w, s4.w, t4.w), 0.f);
            }
        }
        const int brow = bn + grow;
#pragma unroll
        for (int i = 0; i < 4; i++)
            rb[i] = *(const float4*)&B[(size_t)brow * K + k0 + gk + i * 4];
    };

    auto sstore = [&]() {
        const int base = grow * LDS + gk;
#pragma unroll
        for (int i = 0; i < 4; i++) {
            __nv_bfloat16 h0, l0, h1, l1, h2, l2, h3, l3;
            bfsplit(ra[i].x, h0, l0); bfsplit(ra[i].y, h1, l1);
            bfsplit(ra[i].z, h2, l2); bfsplit(ra[i].w, h3, l3);
            *(uint2*)&sAh[base + i * 4] = make_uint2(pkbf(h0, h1), pkbf(h2, h3));
            *(uint2*)&sAl[base + i * 4] = make_uint2(pkbf(l0, l1), pkbf(l2, l3));
            bfsplit(rb[i].x, h0, l0); bfsplit(rb[i].y, h1, l1);
            bfsplit(rb[i].z, h2, l2); bfsplit(rb[i].w, h3, l3);
            *(uint2*)&sBh[base + i * 4] = make_uint2(pkbf(h0, h1), pkbf(h2, h3));
            *(uint2*)&sBl[base + i * 4] = make_uint2(pkbf(l0, l1), pkbf(l2, l3));
        }
    };

    const uint32_t uAh = s2u(sAh), uAl = s2u(sAl);
    const uint32_t uBh = s2u(sBh), uBl = s2u(sBl);

    gload(0);
    constexpr int NT = K / BK;
#pragma unroll 1
    for (int kt = 0; kt < NT; kt++) {
        __syncthreads();
        sstore();
        __syncthreads();
        if (kt + 1 < NT) gload((kt + 1) * BK);

#pragma unroll
        for (int ks = 0; ks < 2; ks++) {
            const int koff = ks * 16 + ((lane & 16) ? 8 : 0);
            uint32_t Bh0[8], Bl0[8];
#pragma unroll
            for (int nf2 = 0; nf2 < 2; nf2++) {
                const int row = nw * 32 + nf2 * 16 + (lane & 15);
                const uint32_t ad = (uint32_t)(row * LDS + koff) * 2;
                ldm_x4(Bh0[nf2*4+0], Bh0[nf2*4+1], Bh0[nf2*4+2], Bh0[nf2*4+3], uBh + ad);
                ldm_x4(Bl0[nf2*4+0], Bl0[nf2*4+1], Bl0[nf2*4+2], Bl0[nf2*4+3], uBl + ad);
            }
#pragma unroll
            for (int mf = 0; mf < 4; mf++) {
                const int arow = mw * 64 + mf * 16 + (lane & 15);
                const uint32_t ad = (uint32_t)(arow * LDS + koff) * 2;
                uint32_t Ah[4], Al[4];
                ldm_x4(Ah[0], Ah[1], Ah[2], Ah[3], uAh + ad);
                ldm_x4(Al[0], Al[1], Al[2], Al[3], uAl + ad);
#pragma unroll
                for (int nf = 0; nf < 4; nf++) {
                    const int b = (nf >> 1) * 4 + (nf & 1);
                    const uint32_t bh0 = Bh0[b], bh1 = Bh0[b + 2];
                    const uint32_t bl0 = Bl0[b], bl1 = Bl0[b + 2];
                    mma_bf16(acc[mf][nf], Ah, bh0, bh1);
                    mma_bf16(acc[mf][nf], Ah, bl0, bl1);
                    mma_bf16(acc[mf][nf], Al, bh0, bh1);
                }
            }
        }
    }

    // epilogue: LAYER 1 -> fp32 store + fused BN stats; LAYER 2 -> fp16 store
#pragma unroll
    for (int mf = 0; mf < 4; mf++) {
        const int r0 = bm + mw * 64 + mf * 16 + (lane >> 2);
        const int r1 = r0 + 8;
#pragma unroll
        for (int nf = 0; nf < 4; nf++) {
            const int col = bn + nw * 32 + nf * 8 + (lane & 3) * 2;
            if (LAYER == 1) {
                if (r0 < M)
                    *(float2*)&d_h1[(size_t)r0 * Ncols + col] =
                        make_float2(acc[mf][nf][0], acc[mf][nf][1]);
                if (r1 < M)
                    *(float2*)&d_h1[(size_t)r1 * Ncols + col] =
                        make_float2(acc[mf][nf][2], acc[mf][nf][3]);
            } else {
                if (r0 < M)
                    *(__half2*)&d_xl2h[(size_t)r0 * Ncols + col] =
                        __floats2half2_rn(acc[mf][nf][0], acc[mf][nf][1]);
                if (r1 < M)
                    *(__half2*)&d_xl2h[(size_t)r1 * Ncols + col] =
                        __floats2half2_rn(acc[mf][nf][2], acc[mf][nf][3]);
            }
        }
    }
    if (LAYER == 1) {
        // per-thread partial sums over its 8 columns (rows >= M contribute 0)
        float s[8], q[8];
#pragma unroll
        for (int c = 0; c < 8; c++) { s[c] = 0.f; q[c] = 0.f; }
#pragma unroll
        for (int mf = 0; mf < 4; mf++)
#pragma unroll
            for (int nf = 0; nf < 4; nf++)
#pragma unroll
                for (int pair = 0; pair < 2; pair++) {
                    const int c = nf * 2 + pair;
                    const float v0 = acc[mf][nf][pair];       // row r0
                    const float v1 = acc[mf][nf][2 + pair];   // row r1
                    s[c] += v0 + v1;
                    q[c] = fmaf(v0, v0, q[c]);
                    q[c] = fmaf(v1, v1, q[c]);
                }
        // reduce across the 8 row-lane groups (lane>>2)
#pragma unroll
        for (int off = 4; off < 32; off <<= 1)
#pragma unroll
            for (int c = 0; c < 8; c++) {
                s[c] += __shfl_xor_sync(0xffffffffu, s[c], off);
                q[c] += __shfl_xor_sync(0xffffffffu, q[c], off);
            }
        if (lane < 4) {
#pragma unroll
            for (int c = 0; c < 8; c++) {
                const int col = bn + nw * 32 + (c >> 1) * 8 + lane * 2 + (c & 1);
                atomicAdd(&d_sum1[col], s[c]);
                atomicAdd(&d_sum1[C_MID + col], q[c]);
            }
        }
    }
}

// ---------------- final: out = relu(a2*h2 + b2 + x), BN affine in-register ---
__global__ __launch_bounds__(256) void k_final(const float* __restrict__ x,
                                               const float* __restrict__ g2,
                                               const float* __restrict__ b2,
                                               float* __restrict__ out) {
    const int idx = blockIdx.x * 256 + threadIdx.x;
    const int f = threadIdx.x;
    const float invN = 1.f / (float)N_NODES;
    const float s = d_sum2[f], q = d_sum2[C_IN + f];
    const float m = s * invN;
    const float a = g2[f] * rsqrtf(q * invN - m * m + 1e-5f);
    const float b = b2[f] - m * a;
    const float v = fmaf(a, d_h2[idx], b) + x[idx];
    out[idx] = fmaxf(v, 0.f);
}

// ---------------- launcher (kernel launches ONLY — graph-capture safe) --------
extern "C" void kernel_launch(void* const* d_in, const int* in_sizes, int n_in,
                              void* d_out, int out_size) {
    (void)in_sizes; (void)n_in; (void)out_size;
    const float* x  = (const float*)d_in[0];
    const int*   es = (const int*)d_in[1];      // int32 edge list [2, E]
    const float* W1 = (const float*)d_in[2];
    const float* g1 = (const float*)d_in[3];
    const float* b1 = (const float*)d_in[4];
    const float* W2 = (const float*)d_in[5];
    const float* g2 = (const float*)d_in[6];
    const float* b2 = (const float*)d_in[7];
    float* out = (float*)d_out;

    // pre: x->fp16 + degree count + BN accumulator reset (d_cnt==0 on entry)
    k_pre<<<(N_NODES * C_IN / 4 + 255) / 256, 256>>>(es, x);
    k_scan<<<1, 1024>>>();
    k_fill<<<(E_EDGES + 255) / 256, 256>>>(es);

    // layer 1: aggregate x (fp16 gather) -> TC GEMM (+BN stats fused)
    k_agg<1><<<(N_NODES + 1) / 2, 128>>>();
    {
        dim3 grid(C_MID / 128, (N_NODES + 127) / 128);   // (4, 79)
        k_gemm<C_IN, 1><<<grid, 256>>>(W1, N_NODES, C_MID, nullptr, nullptr);
    }

    // layer 2: TC GEMM (BN affine in-prologue, fp16 out) -> aggregate -> stats -> out
    {
        dim3 grid(C_IN / 128, (N_NODES + 127) / 128);    // (2, 79)
        k_gemm<C_MID, 2><<<grid, 256>>>(W2, N_NODES, C_IN, g1, b1);
    }
    k_agg<2><<<(N_NODES + 1) / 2, 128>>>();
    k_bnstats2<<<296, 256>>>();
    k_final<<<N_NODES, 256>>>(x, g2, b2, out);
}

// round 16
// speedup vs baseline: 2.2394x; 1.1709x over previous
#include <cuda_runtime.h>
#include <cuda_bf16.h>
#include <cuda_fp16.h>
#include <math.h>
#include <stdint.h>

#define N_NODES 10000
#define E_EDGES 160000
#define C_IN    256
#define C_MID   512

// ---------------- scratch (static __device__ allocations only) ----------------
// Invariant across calls: d_cnt == 0 (restored by k_fill after its readers ran).
// d_sum1/d_sum2 are reset by k_pre at the start of every call.
__device__ __half d_xh [(size_t)N_NODES * C_IN];   // fp16 copy of x (gather operand)
__device__ float d_agx[(size_t)N_NODES * C_IN];    // Â x           (256-wide)
__device__ float d_h1 [(size_t)N_NODES * C_MID];   // (Âx) W1^T     (pre-BN)
__device__ __half d_xl2h[(size_t)N_NODES * C_IN];  // h1n W2^T (fp16 gather operand)
__device__ float d_h2 [(size_t)N_NODES * C_IN];    // Â xl2         (pre-BN)
__device__ int   d_cnt[N_NODES];
__device__ int   d_off[N_NODES + 1];
__device__ int   d_cur[N_NODES];
__device__ float d_dis[N_NODES];                   // deg^-0.5 (incl self loop)
__device__ int   d_esrc[E_EDGES];                  // CSR-by-dst source rows
__device__ float d_sum1[2 * C_MID];                // layer1 BN sums (gemm1 epilogue)
__device__ float d_sum2[2 * C_IN];                 // layer2 BN sums (bnstats2)

// ---------------- helpers ----------------
__device__ __forceinline__ uint32_t s2u(const void* p) {
    return (uint32_t)__cvta_generic_to_shared(p);
}
__device__ __forceinline__ void hsplit(float x, __half& h, __half& l) {
    h = __float2half_rn(x);
    l = __float2half_rn(x - __half2float(h));
}
__device__ __forceinline__ uint32_t pkh(__half a, __half b) {
    __half2 v; v.x = a; v.y = b;
    return *(uint32_t*)&v;
}
__device__ __forceinline__ void ldm_x4(uint32_t& r0, uint32_t& r1, uint32_t& r2,
                                       uint32_t& r3, uint32_t addr) {
    asm volatile("ldmatrix.sync.aligned.m8n8.x4.shared.b16 {%0,%1,%2,%3}, [%4];"
                 : "=r"(r0), "=r"(r1), "=r"(r2), "=r"(r3) : "r"(addr));
}
__device__ __forceinline__ void mma_f16(float* d, const uint32_t* a,
                                        uint32_t b0, uint32_t b1) {
    asm volatile(
        "mma.sync.aligned.m16n8k16.row.col.f32.f16.f16.f32 "
        "{%0,%1,%2,%3}, {%4,%5,%6,%7}, {%8,%9}, {%0,%1,%2,%3};"
        : "+f"(d[0]), "+f"(d[1]), "+f"(d[2]), "+f"(d[3])
        : "r"(a[0]), "r"(a[1]), "r"(a[2]), "r"(a[3]), "r"(b0), "r"(b1));
}

// ---------------- k_pre: x->fp16 + degree count + BN accumulator reset -------
// grid 2500x256 = 640000 threads. d_cnt==0 on entry (invariant).
__global__ __launch_bounds__(256) void k_pre(const int* __restrict__ es,
                                             const float* __restrict__ x) {
    const int t = blockIdx.x * 256 + threadIdx.x;     // 0..639999
    if (t < 2 * C_MID) d_sum1[t] = 0.f;
    else if (t < 2 * C_MID + 2 * C_IN) d_sum2[t - 2 * C_MID] = 0.f;
    {   // fp16 conversion: 4 elements per thread covers N*C_IN = 2.56M
        const float4 v = *(const float4*)&x[t * 4];
        uint2 u;
        *(__half2*)&u.x = __floats2half2_rn(v.x, v.y);
        *(__half2*)&u.y = __floats2half2_rn(v.z, v.w);
        *(uint2*)&d_xh[t * 4] = u;
    }
    if (t < E_EDGES) {
        unsigned c = (unsigned)es[E_EDGES + t];
        if (c < N_NODES) atomicAdd(&d_cnt[c], 1);
    }
}

// ---------------- exclusive scan (single block) + dis ----------------
__global__ void k_scan() {
    __shared__ int sh[1024];
    int t = threadIdx.x;
    const int CH = (N_NODES + 1023) / 1024;  // 10
    int base = t * CH;
    int loc = 0;
    for (int i = 0; i < CH; i++) {
        int idx = base + i;
        if (idx < N_NODES) loc += d_cnt[idx];
    }
    sh[t] = loc;
    __syncthreads();
    for (int s = 1; s < 1024; s <<= 1) {
        int v = (t >= s) ? sh[t - s] : 0;
        __syncthreads();
        sh[t] += v;
        __syncthreads();
    }
    int run = (t == 0) ? 0 : sh[t - 1];
    for (int i = 0; i < CH; i++) {
        int idx = base + i;
        if (idx < N_NODES) {
            d_off[idx] = run;
            d_cur[idx] = run;
            int c = d_cnt[idx];
            d_dis[idx] = rsqrtf((float)(c + 1));   // +1 self loop; always > 0
            run += c;
        }
    }
    if (t == 1023) d_off[N_NODES] = sh[1023];
}

// ---------------- CSR fill + restore d_cnt==0 for next call ----------------
__global__ void k_fill(const int* __restrict__ es) {
    int e = blockIdx.x * blockDim.x + threadIdx.x;
    if (e < N_NODES) d_cnt[e] = 0;     // readers (pre/scan) already ran
    if (e < E_EDGES) {
        unsigned r = (unsigned)es[e];
        unsigned c = (unsigned)es[E_EDGES + e];
        if (r < N_NODES && c < N_NODES) {
            int p = atomicAdd(&d_cur[c], 1);
            d_esrc[p] = (int)r;
        }
    }
}

// ---------------- CSR gather (fp16 rows; 32 thr/node, VEC=8, fp32 accum) -----
// One uint4 (16B) load per edge per thread. 4 nodes per 128-thread block.
// MODE 1: in = d_xh,   out = d_agx.   MODE 2: in = d_xl2h, out = d_h2.
template <int MODE>
__global__ __launch_bounds__(128) void k_agg() {
    const __half* __restrict__ in = (MODE == 1) ? d_xh : d_xl2h;
    float* __restrict__ out = (MODE == 1) ? d_agx : d_h2;

    const int v = blockIdx.x * 4 + (threadIdx.x >> 5);   // 32 threads per node
    const int off = (threadIdx.x & 31) * 8;
    if (v >= N_NODES) return;

    float a[8];
#pragma unroll
    for (int i = 0; i < 8; i++) a[i] = 0.f;
    const int beg = d_off[v], end = d_off[v + 1];
    const float dv = d_dis[v];

    auto acc_row = [&](float w, uint4 u) {
        const float2 f0 = __half22float2(*(const __half2*)&u.x);
        const float2 f1 = __half22float2(*(const __half2*)&u.y);
        const float2 f2 = __half22float2(*(const __half2*)&u.z);
        const float2 f3 = __half22float2(*(const __half2*)&u.w);
        a[0] = fmaf(w, f0.x, a[0]); a[1] = fmaf(w, f0.y, a[1]);
        a[2] = fmaf(w, f1.x, a[2]); a[3] = fmaf(w, f1.y, a[3]);
        a[4] = fmaf(w, f2.x, a[4]); a[5] = fmaf(w, f2.y, a[5]);
        a[6] = fmaf(w, f3.x, a[6]); a[7] = fmaf(w, f3.y, a[7]);
    };

    int e = beg;
    for (; e + 3 < end; e += 4) {
        const int s0 = d_esrc[e + 0], s1 = d_esrc[e + 1];
        const int s2 = d_esrc[e + 2], s3 = d_esrc[e + 3];
        const float w0 = d_dis[s0], w1 = d_dis[s1];
        const float w2 = d_dis[s2], w3 = d_dis[s3];
        const uint4 u0 = *(const uint4*)&in[(size_t)s0 * C_IN + off];
        const uint4 u1 = *(const uint4*)&in[(size_t)s1 * C_IN + off];
        const uint4 u2 = *(const uint4*)&in[(size_t)s2 * C_IN + off];
        const uint4 u3 = *(const uint4*)&in[(size_t)s3 * C_IN + off];
        acc_row(w0, u0); acc_row(w1, u1); acc_row(w2, u2); acc_row(w3, u3);
    }
    for (; e < end; e++) {
        const int s = d_esrc[e];
        acc_row(d_dis[s], *(const uint4*)&in[(size_t)s * C_IN + off]);
    }
    acc_row(dv, *(const uint4*)&in[(size_t)v * C_IN + off]);   // self loop

    float* o = &out[(size_t)v * C_IN + off];
    *(float4*)o       = make_float4(dv * a[0], dv * a[1], dv * a[2], dv * a[3]);
    *(float4*)(o + 4) = make_float4(dv * a[4], dv * a[5], dv * a[6], dv * a[7]);
}

// ---------------- BN stats for layer 2 (streaming pass over d_h2) ------------
__global__ __launch_bounds__(256) void k_bnstats2() {
    float s = 0.f, q = 0.f;
    for (int r = blockIdx.x; r < N_NODES; r += gridDim.x) {
        const float v = d_h2[(size_t)r * C_IN + threadIdx.x];
        s += v; q = fmaf(v, v, q);
    }
    atomicAdd(&d_sum2[threadIdx.x], s);
    atomicAdd(&d_sum2[C_IN + threadIdx.x], q);
}

// ---------------- Tensor-core NT GEMM (fp16 A single, fp16 B split) ----------
// C[M,N] = A[M,K] * B[N,K]^T.  Block 128x128, BK=32, 8 warps (2x4), warp 64x32.
// D += A16*(Bh + Bl)  — 2 MMAs per tile pair.
// LAYER 1: A = d_agx, C = d_h1 (fp32), fused BN-stats atomics into d_sum1.
// LAYER 2: A = d_h1, BN affine in-block from d_sum1/g/be, fused relu(a*v+b)
//          on A-load, C = d_xl2h (fp16).
template <int K, int LAYER>
__global__ __launch_bounds__(256) void k_gemm(const float* __restrict__ B,
                                              int M, int Ncols,
                                              const float* __restrict__ g,
                                              const float* __restrict__ be)
{
    const float* __restrict__ A = (LAYER == 1) ? d_agx : d_h1;

    constexpr int BK  = 32;
    constexpr int LDS = 40;                    // halves per smem row (80B stride)
    __shared__ __half sA16[128 * LDS];
    __shared__ __half sBh [128 * LDS];
    __shared__ __half sBl [128 * LDS];
    __shared__ float sA_[C_MID], sB_[C_MID];   // BN affine (LAYER 2)

    const int bm = blockIdx.y * 128, bn = blockIdx.x * 128;
    const int tid = threadIdx.x;
    const int lane = tid & 31, wid = tid >> 5;
    const int mw = wid >> 2, nw = wid & 3;     // warp grid 2(m) x 4(n)

    if (LAYER == 2) {
        const float invN = 1.f / (float)N_NODES;
#pragma unroll
        for (int f = tid; f < K; f += 256) {
            const float s = d_sum1[f], q = d_sum1[K + f];
            const float m = s * invN;
            const float a = g[f] * rsqrtf(q * invN - m * m + 1e-5f);
            sA_[f] = a;
            sB_[f] = be[f] - m * a;
        }
        __syncthreads();
    }

    float acc[4][4][4];
#pragma unroll
    for (int i = 0; i < 4; i++)
#pragma unroll
        for (int j = 0; j < 4; j++)
#pragma unroll
            for (int q = 0; q < 4; q++) acc[i][j][q] = 0.f;

    const int grow = tid >> 1;                 // 0..127
    const int gk   = (tid & 1) * 16;           // 0 or 16

    float4 ra[4], rb[4];
    auto gload = [&](int k0) {
        const int arow = bm + grow;
        if (arow < M) {
#pragma unroll
            for (int i = 0; i < 4; i++)
                ra[i] = *(const float4*)&A[(size_t)arow * K + k0 + gk + i * 4];
        } else {
#pragma unroll
            for (int i = 0; i < 4; i++) ra[i] = make_float4(0.f, 0.f, 0.f, 0.f);
        }
        if (LAYER == 2) {
#pragma unroll
            for (int i = 0; i < 4; i++) {
                const int kb = k0 + gk + i * 4;
                const float4 s4 = *(const float4*)&sA_[kb];
                const float4 t4 = *(const float4*)&sB_[kb];
                ra[i].x = fmaxf(fmaf(ra[i].x, s4.x, t4.x), 0.f);
                ra[i].y = fmaxf(fmaf(ra[i].y, s4.y, t4.y), 0.f);
                ra[i].z = fmaxf(fmaf(ra[i].z, s4.z, t4.z), 0.f);
                ra[i].w = fmaxf(fmaf(ra[i].w, s4.w, t4.w), 0.f);
            }
        }
        const int brow = bn + grow;
#pragma unroll
        for (int i = 0; i < 4; i++)
            rb[i] = *(const float4*)&B[(size_t)brow * K + k0 + gk + i * 4];
    };

    auto sstore = [&]() {
        const int base = grow * LDS + gk;
#pragma unroll
        for (int i = 0; i < 4; i++) {
            // A: single fp16
            *(uint2*)&sA16[base + i * 4] = make_uint2(
                pkh(__float2half_rn(ra[i].x), __float2half_rn(ra[i].y)),
                pkh(__float2half_rn(ra[i].z), __float2half_rn(ra[i].w)));
            // B: fp16 h + l split
            __half h0, l0, h1, l1, h2, l2, h3, l3;
            hsplit(rb[i].x, h0, l0); hsplit(rb[i].y, h1, l1);
            hsplit(rb[i].z, h2, l2); hsplit(rb[i].w, h3, l3);
            *(uint2*)&sBh[base + i * 4] = make_uint2(pkh(h0, h1), pkh(h2, h3));
            *(uint2*)&sBl[base + i * 4] = make_uint2(pkh(l0, l1), pkh(l2, l3));
        }
    };

    const uint32_t uA16 = s2u(sA16);
    const uint32_t uBh = s2u(sBh), uBl = s2u(sBl);

    gload(0);
    constexpr int NT = K / BK;
#pragma unroll 1
    for (int kt = 0; kt < NT; kt++) {
        __syncthreads();
        sstore();
        __syncthreads();
        if (kt + 1 < NT) gload((kt + 1) * BK);

#pragma unroll
        for (int ks = 0; ks < 2; ks++) {
            const int koff = ks * 16 + ((lane & 16) ? 8 : 0);
            uint32_t Bh0[8], Bl0[8];
#pragma unroll
            for (int nf2 = 0; nf2 < 2; nf2++) {
                const int row = nw * 32 + nf2 * 16 + (lane & 15);
                const uint32_t ad = (uint32_t)(row * LDS + koff) * 2;
                ldm_x4(Bh0[nf2*4+0], Bh0[nf2*4+1], Bh0[nf2*4+2], Bh0[nf2*4+3], uBh + ad);
                ldm_x4(Bl0[nf2*4+0], Bl0[nf2*4+1], Bl0[nf2*4+2], Bl0[nf2*4+3], uBl + ad);
            }
#pragma unroll
            for (int mf = 0; mf < 4; mf++) {
                const int arow = mw * 64 + mf * 16 + (lane & 15);
                const uint32_t ad = (uint32_t)(arow * LDS + koff) * 2;
                uint32_t Ah[4];
                ldm_x4(Ah[0], Ah[1], Ah[2], Ah[3], uA16 + ad);
#pragma unroll
                for (int nf = 0; nf < 4; nf++) {
                    const int b = (nf >> 1) * 4 + (nf & 1);
                    mma_f16(acc[mf][nf], Ah, Bh0[b], Bh0[b + 2]);
                    mma_f16(acc[mf][nf], Ah, Bl0[b], Bl0[b + 2]);
                }
            }
        }
    }

    // epilogue: LAYER 1 -> fp32 store + fused BN stats; LAYER 2 -> fp16 store
#pragma unroll
    for (int mf = 0; mf < 4; mf++) {
        const int r0 = bm + mw * 64 + mf * 16 + (lane >> 2);
        const int r1 = r0 + 8;
#pragma unroll
        for (int nf = 0; nf < 4; nf++) {
            const int col = bn + nw * 32 + nf * 8 + (lane & 3) * 2;
            if (LAYER == 1) {
                if (r0 < M)
                    *(float2*)&d_h1[(size_t)r0 * Ncols + col] =
                        make_float2(acc[mf][nf][0], acc[mf][nf][1]);
                if (r1 < M)
                    *(float2*)&d_h1[(size_t)r1 * Ncols + col] =
                        make_float2(acc[mf][nf][2], acc[mf][nf][3]);
            } else {
                if (r0 < M)
                    *(__half2*)&d_xl2h[(size_t)r0 * Ncols + col] =
                        __floats2half2_rn(acc[mf][nf][0], acc[mf][nf][1]);
                if (r1 < M)
                    *(__half2*)&d_xl2h[(size_t)r1 * Ncols + col] =
                        __floats2half2_rn(acc[mf][nf][2], acc[mf][nf][3]);
            }
        }
    }
    if (LAYER == 1) {
        // per-thread partial sums over its 8 columns (rows >= M contribute 0)
        float s[8], q[8];
#pragma unroll
        for (int c = 0; c < 8; c++) { s[c] = 0.f; q[c] = 0.f; }
#pragma unroll
        for (int mf = 0; mf < 4; mf++)
#pragma unroll
            for (int nf = 0; nf < 4; nf++)
#pragma unroll
                for (int pair = 0; pair < 2; pair++) {
                    const int c = nf * 2 + pair;
                    const float v0 = acc[mf][nf][pair];       // row r0
                    const float v1 = acc[mf][nf][2 + pair];   // row r1
                    s[c] += v0 + v1;
                    q[c] = fmaf(v0, v0, q[c]);
                    q[c] = fmaf(v1, v1, q[c]);
                }
        // reduce across the 8 row-lane groups (lane>>2)
#pragma unroll
        for (int off = 4; off < 32; off <<= 1)
#pragma unroll
            for (int c = 0; c < 8; c++) {
                s[c] += __shfl_xor_sync(0xffffffffu, s[c], off);
                q[c] += __shfl_xor_sync(0xffffffffu, q[c], off);
            }
        if (lane < 4) {
#pragma unroll
            for (int c = 0; c < 8; c++) {
                const int col = bn + nw * 32 + (c >> 1) * 8 + lane * 2 + (c & 1);
                atomicAdd(&d_sum1[col], s[c]);
                atomicAdd(&d_sum1[C_MID + col], q[c]);
            }
        }
    }
}

// ---------------- final: out = relu(a2*h2 + b2 + x), BN affine in-register ---
__global__ __launch_bounds__(256) void k_final(const float* __restrict__ x,
                                               const float* __restrict__ g2,
                                               const float* __restrict__ b2,
                                               float* __restrict__ out) {
    const int idx = blockIdx.x * 256 + threadIdx.x;
    const int f = threadIdx.x;
    const float invN = 1.f / (float)N_NODES;
    const float s = d_sum2[f], q = d_sum2[C_IN + f];
    const float m = s * invN;
    const float a = g2[f] * rsqrtf(q * invN - m * m + 1e-5f);
    const float b = b2[f] - m * a;
    const float v = fmaf(a, d_h2[idx], b) + x[idx];
    out[idx] = fmaxf(v, 0.f);
}

// ---------------- launcher (kernel launches ONLY — graph-capture safe) --------
extern "C" void kernel_launch(void* const* d_in, const int* in_sizes, int n_in,
                              void* d_out, int out_size) {
    (void)in_sizes; (void)n_in; (void)out_size;
    const float* x  = (const float*)d_in[0];
    const int*   es = (const int*)d_in[1];      // int32 edge list [2, E]
    const float* W1 = (const float*)d_in[2];
    const float* g1 = (const float*)d_in[3];
    const float* b1 = (const float*)d_in[4];
    const float* W2 = (const float*)d_in[5];
    const float* g2 = (const float*)d_in[6];
    const float* b2 = (const float*)d_in[7];
    float* out = (float*)d_out;

    // pre: x->fp16 + degree count + BN accumulator reset (d_cnt==0 on entry)
    k_pre<<<(N_NODES * C_IN / 4 + 255) / 256, 256>>>(es, x);
    k_scan<<<1, 1024>>>();
    k_fill<<<(E_EDGES + 255) / 256, 256>>>(es);

    // layer 1: aggregate x (fp16 gather) -> TC GEMM (+BN stats fused)
    k_agg<1><<<(N_NODES + 3) / 4, 128>>>();
    {
        dim3 grid(C_MID / 128, (N_NODES + 127) / 128);   // (4, 79)
        k_gemm<C_IN, 1><<<grid, 256>>>(W1, N_NODES, C_MID, nullptr, nullptr);
    }

    // layer 2: TC GEMM (BN affine in-prologue, fp16 out) -> aggregate -> stats -> out
    {
        dim3 grid(C_IN / 128, (N_NODES + 127) / 128);    // (2, 79)
        k_gemm<C_MID, 2><<<grid, 256>>>(W2, N_NODES, C_IN, g1, b1);
    }
    k_agg<2><<<(N_NODES + 3) / 4, 128>>>();
    k_bnstats2<<<296, 256>>>();
    k_final<<<N_NODES, 256>>>(x, g2, b2, out);
}